// round 10
// baseline (speedup 1.0000x reference)
#include <cuda_runtime.h>
#include <cuda_bf16.h>
#include <mma.h>
#include <stdint.h>

using namespace nvcuda;

#define NN  50000
#define EE  800000
#define NBLK 196            // ceil(NN/256)
#define NPAD (NN + 128)     // row padding: wmma stores / unguarded A reads stay in-bounds

// W split storage offsets (bf16 elements): layer0 128x128, layer1 128x128, layer2 128x64
#define WOFF0 0
#define WOFF1 16384
#define WOFF2 32768
#define WTOTAL 40960

// ---------------- scratch (device globals, zero-init at load) ---------------
__device__ __align__(16) float g_t[NPAD * 128];
__device__ __align__(16) float g_r[NPAD * 128];
__device__ __align__(16) __nv_bfloat16 g_xhi[NPAD * 128];  // split of x
__device__ __align__(16) __nv_bfloat16 g_xlo[NPAD * 128];
__device__ __align__(16) __nv_bfloat16 g_ahi[NPAD * 128];  // split of activations
__device__ __align__(16) __nv_bfloat16 g_alo[NPAD * 128];
__device__ __align__(16) __nv_bfloat16 g_whl_hi[WTOTAL];   // Wl splits, all layers
__device__ __align__(16) __nv_bfloat16 g_whl_lo[WTOTAL];
__device__ __align__(16) __nv_bfloat16 g_whr_hi[WTOTAL];   // Wr splits
__device__ __align__(16) __nv_bfloat16 g_whr_lo[WTOTAL];
__device__ int   g_degc[NN];
__device__ int   g_rowoff[NN + 1];
__device__ int   g_wptr[NN];
__device__ int   g_csr[EE];
__device__ float g_invdeg[NN];
__device__ int   g_bsum[NBLK];
__device__ int   g_bpre[NBLK];

// ---------------- bf16 split helper ------------------------------------------
__device__ __forceinline__ void split_bf16(float v, __nv_bfloat16& h, __nv_bfloat16& l) {
    h = __float2bfloat16(v);
    l = __float2bfloat16(v - __bfloat162float(h));
}

// ---------------- edge dtype probe --------------------------------------------
__device__ __forceinline__ int probe_is64(const void* ei) {
    int lane = threadIdx.x & 31;
    long long v = ((const long long*)ei)[lane];
    unsigned ok = __ballot_sync(0xffffffffu, v >= 0 && v < NN);
    return ok == 0xffffffffu;
}

__device__ __forceinline__ void load_edge(const void* ei, int e, int is64,
                                          int& s, int& d) {
    if (is64) {
        const long long* p = (const long long*)ei;
        s = (int)p[e];
        d = (int)p[EE + e];
    } else {
        const int* p = (const int*)ei;
        s = p[e];
        d = p[EE + e];
    }
    s = min(max(s, 0), NN - 1);
    d = min(max(d, 0), NN - 1);
}

// ---------------- one-time-per-launch splits ---------------------------------
__global__ void split_x_kernel(const float* __restrict__ x) {
    int i = blockIdx.x * blockDim.x + threadIdx.x;   // float4 index
    if (i >= NN * 32) return;
    float4 v = ((const float4*)x)[i];
    __nv_bfloat16 h[4], l[4];
    split_bf16(v.x, h[0], l[0]); split_bf16(v.y, h[1], l[1]);
    split_bf16(v.z, h[2], l[2]); split_bf16(v.w, h[3], l[3]);
    *(uint2*)(g_xhi + (size_t)i * 4) = *(uint2*)h;
    *(uint2*)(g_xlo + (size_t)i * 4) = *(uint2*)l;
}

__global__ void split_w_kernel(const float* __restrict__ wl0, const float* __restrict__ wr0,
                               const float* __restrict__ wl1, const float* __restrict__ wr1,
                               const float* __restrict__ wl2, const float* __restrict__ wr2) {
    int idx = blockIdx.x * blockDim.x + threadIdx.x;
    if (idx >= WTOTAL) return;
    const float *wl, *wr;
    int local;
    if (idx < WOFF1)      { wl = wl0; wr = wr0; local = idx; }
    else if (idx < WOFF2) { wl = wl1; wr = wr1; local = idx - WOFF1; }
    else                  { wl = wl2; wr = wr2; local = idx - WOFF2; }
    __nv_bfloat16 h, l;
    split_bf16(wl[local], h, l);
    g_whl_hi[idx] = h; g_whl_lo[idx] = l;
    split_bf16(wr[local], h, l);
    g_whr_hi[idx] = h; g_whr_lo[idx] = l;
}

// ---------------- graph preprocessing -----------------------------------------
__global__ void count_deg_kernel(const void* __restrict__ ei) {
    int is64 = probe_is64(ei);
    int e = blockIdx.x * blockDim.x + threadIdx.x;
    if (e < EE) {
        int s, d;
        load_edge(ei, e, is64, s, d);
        atomicAdd(&g_degc[d], 1);
    }
}

__global__ void blocksum_kernel() {
    int i = blockIdx.x * 256 + threadIdx.x;
    int v = (i < NN) ? g_degc[i] : 0;
#pragma unroll
    for (int off = 16; off > 0; off >>= 1)
        v += __shfl_down_sync(0xffffffffu, v, off);
    __shared__ int ws[8];
    if ((threadIdx.x & 31) == 0) ws[threadIdx.x >> 5] = v;
    __syncthreads();
    if (threadIdx.x == 0) {
        int s = 0;
#pragma unroll
        for (int w = 0; w < 8; w++) s += ws[w];
        g_bsum[blockIdx.x] = s;
    }
}

__global__ void scan_bsum_kernel() {
    __shared__ int sh[256];
    int t = threadIdx.x;
    int v = (t < NBLK) ? g_bsum[t] : 0;
    sh[t] = v;
    __syncthreads();
#pragma unroll
    for (int off = 1; off < 256; off <<= 1) {
        int u = (t >= off) ? sh[t - off] : 0;
        __syncthreads();
        sh[t] += u;
        __syncthreads();
    }
    if (t < NBLK) g_bpre[t] = sh[t] - v;
    if (t == NBLK - 1) g_rowoff[NN] = sh[t];
}

__global__ void write_off_kernel() {
    __shared__ int sh[256];
    int t = threadIdx.x;
    int i = blockIdx.x * 256 + t;
    int v = (i < NN) ? g_degc[i] : 0;
    sh[t] = v;
    __syncthreads();
#pragma unroll
    for (int off = 1; off < 256; off <<= 1) {
        int u = (t >= off) ? sh[t - off] : 0;
        __syncthreads();
        sh[t] += u;
        __syncthreads();
    }
    if (i < NN) {
        int excl = g_bpre[blockIdx.x] + sh[t] - v;
        g_rowoff[i] = excl;
        g_wptr[i]   = excl;
        g_invdeg[i] = 1.0f / fmaxf((float)v, 1.0f);
        g_degc[i]   = 0;
    }
}

__global__ void fill_csr_kernel(const void* __restrict__ ei) {
    int is64 = probe_is64(ei);
    int e = blockIdx.x * blockDim.x + threadIdx.x;
    if (e < EE) {
        int s, d;
        load_edge(ei, e, is64, s, d);
        int p = atomicAdd(&g_wptr[d], 1);
        if (p >= 0 && p < EE) g_csr[p] = s;
    }
}

// ---------------- wmma bf16 split GEMM (copy-only staging) ------------------
// CTA: 128 rows x COLT cols; blockIdx.y: 0 -> Wl->g_t, 1 -> Wr->g_r.
// 8 warps 4m x 2n; warp tile 32m x (COLT/2)n. 3-term split MMA, fp32 acc.
// A hi/lo and W hi/lo are PRE-SPLIT bf16 in device globals; pointers resolved
// IN DEVICE CODE (useX selects g_x* vs g_a*) -- device globals must never be
// passed as kernel arguments from host.
#define KCH 32
#define KP  40     // A smem row stride (bf16 elems)

template <int COLT>   // 128 or 64
__global__ __launch_bounds__(256)
void gemm_wmma_kernel(int useX, int wOff) {
    constexpr int CP = COLT + 8;
    constexpr int NF = COLT / 32;     // 16-col frags per warp (4 or 2)

    __shared__ __align__(16) __nv_bfloat16 Ahi[128 * KP];
    __shared__ __align__(16) __nv_bfloat16 Alo[128 * KP];
    __shared__ __align__(16) __nv_bfloat16 Whi[KCH * CP];
    __shared__ __align__(16) __nv_bfloat16 Wlo[KCH * CP];

    const __nv_bfloat16* ahi = useX ? g_xhi : g_ahi;
    const __nv_bfloat16* alo = useX ? g_xlo : g_alo;
    const __nv_bfloat16* whi = (blockIdx.y ? g_whr_hi : g_whl_hi) + wOff;
    const __nv_bfloat16* wlo = (blockIdx.y ? g_whr_lo : g_whl_lo) + wOff;
    float* Cout = blockIdx.y ? g_r : g_t;

    const int tid = threadIdx.x;
    const int wid = tid >> 5;
    const int wm = wid & 3;           // m-tile 0..3
    const int wn = wid >> 2;          // n-half 0..1
    const int rowBase = blockIdx.x * 128;

    wmma::fragment<wmma::accumulator, 16, 16, 16, float> acc[2][NF];
#pragma unroll
    for (int m = 0; m < 2; m++)
#pragma unroll
        for (int f = 0; f < NF; f++) wmma::fill_fragment(acc[m][f], 0.0f);

    const int arow = tid >> 1;            // 0..127
    const int akq  = (tid & 1) * 16;      // 0 or 16

    for (int kc = 0; kc < 128; kc += KCH) {
        // ---- stage A chunk: pure vector copies (rows < NPAD always valid) ----
        {
            size_t gsrc = (size_t)(rowBase + arow) * 128 + kc + akq;
            const uint4* sh = (const uint4*)(ahi + gsrc);
            const uint4* sl = (const uint4*)(alo + gsrc);
            uint4* dh = (uint4*)(Ahi + arow * KP + akq);
            uint4* dl = (uint4*)(Alo + arow * KP + akq);
            dh[0] = sh[0]; dh[1] = sh[1];
            dl[0] = sl[0]; dl[1] = sl[1];
        }
        // ---- stage W chunk: pure vector copies ----
#pragma unroll
        for (int f = tid; f < KCH * (COLT / 8); f += 256) {
            int k = f / (COLT / 8);
            int n = (f % (COLT / 8)) * 8;
            size_t gsrc = (size_t)(kc + k) * COLT + n;
            *(uint4*)(Whi + k * CP + n) = *(const uint4*)(whi + gsrc);
            *(uint4*)(Wlo + k * CP + n) = *(const uint4*)(wlo + gsrc);
        }
        __syncthreads();

#pragma unroll
        for (int kk = 0; kk < KCH; kk += 16) {
            wmma::fragment<wmma::matrix_a, 16, 16, 16, __nv_bfloat16,
                           wmma::row_major> ah0, ah1, al0, al1;
            wmma::load_matrix_sync(ah0, Ahi + (wm * 32) * KP + kk, KP);
            wmma::load_matrix_sync(ah1, Ahi + (wm * 32 + 16) * KP + kk, KP);
            wmma::load_matrix_sync(al0, Alo + (wm * 32) * KP + kk, KP);
            wmma::load_matrix_sync(al1, Alo + (wm * 32 + 16) * KP + kk, KP);
#pragma unroll
            for (int f = 0; f < NF; f++) {
                wmma::fragment<wmma::matrix_b, 16, 16, 16, __nv_bfloat16,
                               wmma::row_major> bh, bl;
                int ncol = wn * (COLT / 2) + f * 16;
                wmma::load_matrix_sync(bh, Whi + kk * CP + ncol, CP);
                wmma::load_matrix_sync(bl, Wlo + kk * CP + ncol, CP);
                wmma::mma_sync(acc[0][f], ah0, bh, acc[0][f]);
                wmma::mma_sync(acc[1][f], ah1, bh, acc[1][f]);
                wmma::mma_sync(acc[0][f], ah0, bl, acc[0][f]);
                wmma::mma_sync(acc[1][f], ah1, bl, acc[1][f]);
                wmma::mma_sync(acc[0][f], al0, bh, acc[0][f]);
                wmma::mma_sync(acc[1][f], al1, bh, acc[1][f]);
            }
        }
        __syncthreads();
    }

#pragma unroll
    for (int m = 0; m < 2; m++) {
        int r = rowBase + wm * 32 + m * 16;
#pragma unroll
        for (int f = 0; f < NF; f++) {
            int c = wn * (COLT / 2) + f * 16;
            wmma::store_matrix_sync(Cout + (size_t)r * COLT + c, acc[m][f],
                                    COLT, wmma::mem_row_major);
        }
    }
}

// ---------------- aggregation + combine --------------------------------------
// D==128 (hidden): writes bf16 hi/lo splits to g_ahi/g_alo (next GEMM's input).
// D==64 (final):   writes fp32 to outp.
template <int D, bool RELU>
__global__ __launch_bounds__(256)
void combine_kernel(const float* __restrict__ bias, float* __restrict__ outp) {
    int gw = (blockIdx.x * blockDim.x + threadIdx.x) >> 5;
    int lane = threadIdx.x & 31;
    if (gw >= NN) return;

    int beg = g_rowoff[gw];
    int end = g_rowoff[gw + 1];

    if (D == 128) {
        float4 acc = make_float4(0.f, 0.f, 0.f, 0.f);
        const float* t = g_t;
        int j = beg;
        for (; j + 4 <= end; j += 4) {
            int s0 = g_csr[j], s1 = g_csr[j + 1], s2 = g_csr[j + 2], s3 = g_csr[j + 3];
            float4 v0 = *(const float4*)(t + (size_t)s0 * 128 + lane * 4);
            float4 v1 = *(const float4*)(t + (size_t)s1 * 128 + lane * 4);
            float4 v2 = *(const float4*)(t + (size_t)s2 * 128 + lane * 4);
            float4 v3 = *(const float4*)(t + (size_t)s3 * 128 + lane * 4);
            acc.x += v0.x + v1.x + v2.x + v3.x;
            acc.y += v0.y + v1.y + v2.y + v3.y;
            acc.z += v0.z + v1.z + v2.z + v3.z;
            acc.w += v0.w + v1.w + v2.w + v3.w;
        }
        for (; j < end; j++) {
            int s = g_csr[j];
            float4 v = *(const float4*)(t + (size_t)s * 128 + lane * 4);
            acc.x += v.x; acc.y += v.y; acc.z += v.z; acc.w += v.w;
        }
        float inv = g_invdeg[gw];
        float4 rr = *(const float4*)(g_r + (size_t)gw * 128 + lane * 4);
        float o[4];
        o[0] = acc.x * inv + bias[lane * 4 + 0] + rr.x;
        o[1] = acc.y * inv + bias[lane * 4 + 1] + rr.y;
        o[2] = acc.z * inv + bias[lane * 4 + 2] + rr.z;
        o[3] = acc.w * inv + bias[lane * 4 + 3] + rr.w;
        __nv_bfloat16 h[4], l[4];
#pragma unroll
        for (int e = 0; e < 4; e++) {
            float v = RELU ? fmaxf(o[e], 0.f) : o[e];
            split_bf16(v, h[e], l[e]);
        }
        size_t dst = (size_t)gw * 128 + lane * 4;
        *(uint2*)(g_ahi + dst) = *(uint2*)h;
        *(uint2*)(g_alo + dst) = *(uint2*)l;
    } else {
        float2 acc = make_float2(0.f, 0.f);
        const float* t = g_t;
        int j = beg;
        for (; j + 4 <= end; j += 4) {
            int s0 = g_csr[j], s1 = g_csr[j + 1], s2 = g_csr[j + 2], s3 = g_csr[j + 3];
            float2 v0 = *(const float2*)(t + (size_t)s0 * 64 + lane * 2);
            float2 v1 = *(const float2*)(t + (size_t)s1 * 64 + lane * 2);
            float2 v2 = *(const float2*)(t + (size_t)s2 * 64 + lane * 2);
            float2 v3 = *(const float2*)(t + (size_t)s3 * 64 + lane * 2);
            acc.x += v0.x + v1.x + v2.x + v3.x;
            acc.y += v0.y + v1.y + v2.y + v3.y;
        }
        for (; j < end; j++) {
            int s = g_csr[j];
            float2 v = *(const float2*)(t + (size_t)s * 64 + lane * 2);
            acc.x += v.x; acc.y += v.y;
        }
        float inv = g_invdeg[gw];
        float2 rr = *(const float2*)(g_r + (size_t)gw * 64 + lane * 2);
        float2 o;
        o.x = acc.x * inv + bias[lane * 2 + 0] + rr.x;
        o.y = acc.y * inv + bias[lane * 2 + 1] + rr.y;
        if (RELU) { o.x = fmaxf(o.x, 0.f); o.y = fmaxf(o.y, 0.f); }
        *(float2*)(outp + (size_t)gw * 64 + lane * 2) = o;
    }
}

// ---------------- launch --------------------------------------------------------
extern "C" void kernel_launch(void* const* d_in, const int* in_sizes, int n_in,
                              void* d_out, int out_size) {
    const float* x    = (const float*)d_in[0];
    const void*  ei   = d_in[1];
    const float* w_l0 = (const float*)d_in[2];
    const float* b0   = (const float*)d_in[3];
    const float* w_r0 = (const float*)d_in[4];
    const float* w_l1 = (const float*)d_in[5];
    const float* b1   = (const float*)d_in[6];
    const float* w_r1 = (const float*)d_in[7];
    const float* w_l2 = (const float*)d_in[8];
    const float* b2   = (const float*)d_in[9];
    const float* w_r2 = (const float*)d_in[10];
    float* outp = (float*)d_out;

    const int gemmBlocks = (NN + 127) / 128;      // 391
    const int combBlocks = (NN * 32 + 255) / 256; // 6250

    // splits first, then prep; gemm layer-0 kept at launch #4 (ncu slot)
    split_x_kernel<<<(NN * 32 + 255) / 256, 256>>>(x);
    split_w_kernel<<<(WTOTAL + 255) / 256, 256>>>(w_l0, w_r0, w_l1, w_r1, w_l2, w_r2);
    count_deg_kernel<<<(EE + 255) / 256, 256>>>(ei);
    gemm_wmma_kernel<128><<<dim3(gemmBlocks, 2), 256>>>(1, WOFF0);
    blocksum_kernel<<<NBLK, 256>>>();
    scan_bsum_kernel<<<1, 256>>>();
    write_off_kernel<<<NBLK, 256>>>();
    fill_csr_kernel<<<(EE + 255) / 256, 256>>>(ei);
    combine_kernel<128, true><<<combBlocks, 256>>>(b0, nullptr);
    gemm_wmma_kernel<128><<<dim3(gemmBlocks, 2), 256>>>(0, WOFF1);
    combine_kernel<128, true><<<combBlocks, 256>>>(b1, nullptr);
    gemm_wmma_kernel<64><<<dim3(gemmBlocks, 2), 256>>>(0, WOFF2);
    combine_kernel<64, false><<<combBlocks, 256>>>(b2, outp);
}

// round 11
// speedup vs baseline: 1.0467x; 1.0467x over previous
#include <cuda_runtime.h>
#include <cuda_bf16.h>
#include <mma.h>
#include <stdint.h>

using namespace nvcuda;

#define NN  50000
#define EE  800000
#define NBLK 196            // ceil(NN/256)
#define NPAD (NN + 128)     // row padding: wmma stores / unguarded A reads stay in-bounds

// W split storage offsets (bf16 elements): layer0 128x128, layer1 128x128, layer2 128x64
#define WOFF0 0
#define WOFF1 16384
#define WOFF2 32768
#define WTOTAL 40960

// ---------------- scratch (device globals, zero-init at load) ---------------
__device__ __align__(16) float g_t[NPAD * 128];
__device__ __align__(16) float g_r[NPAD * 128];
__device__ __align__(16) __nv_bfloat16 g_xhi[NPAD * 128];  // split of x
__device__ __align__(16) __nv_bfloat16 g_xlo[NPAD * 128];
__device__ __align__(16) __nv_bfloat16 g_ahi[NPAD * 128];  // split of activations
__device__ __align__(16) __nv_bfloat16 g_alo[NPAD * 128];
__device__ __align__(16) __nv_bfloat16 g_whl_hi[WTOTAL];   // Wl splits, all layers
__device__ __align__(16) __nv_bfloat16 g_whl_lo[WTOTAL];
__device__ __align__(16) __nv_bfloat16 g_whr_hi[WTOTAL];   // Wr splits
__device__ __align__(16) __nv_bfloat16 g_whr_lo[WTOTAL];
__device__ int   g_degc[NN];
__device__ int   g_rowoff[NN + 1];
__device__ int   g_wptr[NN];
__device__ int   g_csr[EE];
__device__ float g_invdeg[NN];
__device__ int   g_bsum[NBLK];
__device__ int   g_bpre[NBLK];

// ---------------- bf16 split helper ------------------------------------------
__device__ __forceinline__ void split_bf16(float v, __nv_bfloat16& h, __nv_bfloat16& l) {
    h = __float2bfloat16(v);
    l = __float2bfloat16(v - __bfloat162float(h));
}

// ---------------- edge dtype probe --------------------------------------------
__device__ __forceinline__ int probe_is64(const void* ei) {
    int lane = threadIdx.x & 31;
    long long v = ((const long long*)ei)[lane];
    unsigned ok = __ballot_sync(0xffffffffu, v >= 0 && v < NN);
    return ok == 0xffffffffu;
}

__device__ __forceinline__ void load_edge(const void* ei, int e, int is64,
                                          int& s, int& d) {
    if (is64) {
        const long long* p = (const long long*)ei;
        s = (int)p[e];
        d = (int)p[EE + e];
    } else {
        const int* p = (const int*)ei;
        s = p[e];
        d = p[EE + e];
    }
    s = min(max(s, 0), NN - 1);
    d = min(max(d, 0), NN - 1);
}

// ---------------- one-time-per-launch splits ---------------------------------
__global__ void split_x_kernel(const float* __restrict__ x) {
    int i = blockIdx.x * blockDim.x + threadIdx.x;   // float4 index
    if (i >= NN * 32) return;
    float4 v = ((const float4*)x)[i];
    __nv_bfloat16 h[4], l[4];
    split_bf16(v.x, h[0], l[0]); split_bf16(v.y, h[1], l[1]);
    split_bf16(v.z, h[2], l[2]); split_bf16(v.w, h[3], l[3]);
    *(uint2*)(g_xhi + (size_t)i * 4) = *(uint2*)h;
    *(uint2*)(g_xlo + (size_t)i * 4) = *(uint2*)l;
}

__global__ void split_w_kernel(const float* __restrict__ wl0, const float* __restrict__ wr0,
                               const float* __restrict__ wl1, const float* __restrict__ wr1,
                               const float* __restrict__ wl2, const float* __restrict__ wr2) {
    int idx = blockIdx.x * blockDim.x + threadIdx.x;
    if (idx >= WTOTAL) return;
    const float *wl, *wr;
    int local;
    if (idx < WOFF1)      { wl = wl0; wr = wr0; local = idx; }
    else if (idx < WOFF2) { wl = wl1; wr = wr1; local = idx - WOFF1; }
    else                  { wl = wl2; wr = wr2; local = idx - WOFF2; }
    __nv_bfloat16 h, l;
    split_bf16(wl[local], h, l);
    g_whl_hi[idx] = h; g_whl_lo[idx] = l;
    split_bf16(wr[local], h, l);
    g_whr_hi[idx] = h; g_whr_lo[idx] = l;
}

// ---------------- graph preprocessing -----------------------------------------
__global__ void count_deg_kernel(const void* __restrict__ ei) {
    int is64 = probe_is64(ei);
    int e = blockIdx.x * blockDim.x + threadIdx.x;
    if (e < EE) {
        int s, d;
        load_edge(ei, e, is64, s, d);
        atomicAdd(&g_degc[d], 1);
    }
}

__global__ void blocksum_kernel() {
    int i = blockIdx.x * 256 + threadIdx.x;
    int v = (i < NN) ? g_degc[i] : 0;
#pragma unroll
    for (int off = 16; off > 0; off >>= 1)
        v += __shfl_down_sync(0xffffffffu, v, off);
    __shared__ int ws[8];
    if ((threadIdx.x & 31) == 0) ws[threadIdx.x >> 5] = v;
    __syncthreads();
    if (threadIdx.x == 0) {
        int s = 0;
#pragma unroll
        for (int w = 0; w < 8; w++) s += ws[w];
        g_bsum[blockIdx.x] = s;
    }
}

__global__ void scan_bsum_kernel() {
    __shared__ int sh[256];
    int t = threadIdx.x;
    int v = (t < NBLK) ? g_bsum[t] : 0;
    sh[t] = v;
    __syncthreads();
#pragma unroll
    for (int off = 1; off < 256; off <<= 1) {
        int u = (t >= off) ? sh[t - off] : 0;
        __syncthreads();
        sh[t] += u;
        __syncthreads();
    }
    if (t < NBLK) g_bpre[t] = sh[t] - v;
    if (t == NBLK - 1) g_rowoff[NN] = sh[t];
}

__global__ void write_off_kernel() {
    __shared__ int sh[256];
    int t = threadIdx.x;
    int i = blockIdx.x * 256 + t;
    int v = (i < NN) ? g_degc[i] : 0;
    sh[t] = v;
    __syncthreads();
#pragma unroll
    for (int off = 1; off < 256; off <<= 1) {
        int u = (t >= off) ? sh[t - off] : 0;
        __syncthreads();
        sh[t] += u;
        __syncthreads();
    }
    if (i < NN) {
        int excl = g_bpre[blockIdx.x] + sh[t] - v;
        g_rowoff[i] = excl;
        g_wptr[i]   = excl;
        g_invdeg[i] = 1.0f / fmaxf((float)v, 1.0f);
        g_degc[i]   = 0;
    }
}

__global__ void fill_csr_kernel(const void* __restrict__ ei) {
    int is64 = probe_is64(ei);
    int e = blockIdx.x * blockDim.x + threadIdx.x;
    if (e < EE) {
        int s, d;
        load_edge(ei, e, is64, s, d);
        int p = atomicAdd(&g_wptr[d], 1);
        if (p >= 0 && p < EE) g_csr[p] = s;
    }
}

// ---------------- wmma bf16 split GEMM (copy-only staging, 2 CTAs/SM) -------
// CTA: 128 rows x COLT cols; blockIdx.y: 0 -> Wl->g_t, 1 -> Wr->g_r.
// 8 warps 4m x 2n; warp tile 32m x (COLT/2)n. 3-term split MMA, fp32 acc.
// __launch_bounds__(256, 2) pins regs <= 128 so 2 CTAs fit per SM — round 10
// measured regs=139 -> 1 CTA/SM -> occupancy cliff (occ 12.4%, issue 15%).
#define KCH 32
#define KP  40     // A smem row stride (bf16 elems)

template <int COLT>   // 128 or 64
__global__ __launch_bounds__(256, 2)
void gemm_wmma_kernel(int useX, int wOff) {
    constexpr int CP = COLT + 8;
    constexpr int NF = COLT / 32;     // 16-col frags per warp (4 or 2)

    __shared__ __align__(16) __nv_bfloat16 Ahi[128 * KP];
    __shared__ __align__(16) __nv_bfloat16 Alo[128 * KP];
    __shared__ __align__(16) __nv_bfloat16 Whi[KCH * CP];
    __shared__ __align__(16) __nv_bfloat16 Wlo[KCH * CP];

    const __nv_bfloat16* ahi = useX ? g_xhi : g_ahi;
    const __nv_bfloat16* alo = useX ? g_xlo : g_alo;
    const __nv_bfloat16* whi = (blockIdx.y ? g_whr_hi : g_whl_hi) + wOff;
    const __nv_bfloat16* wlo = (blockIdx.y ? g_whr_lo : g_whl_lo) + wOff;
    float* Cout = blockIdx.y ? g_r : g_t;

    const int tid = threadIdx.x;
    const int wid = tid >> 5;
    const int wm = wid & 3;           // m-tile 0..3
    const int wn = wid >> 2;          // n-half 0..1
    const int rowBase = blockIdx.x * 128;

    wmma::fragment<wmma::accumulator, 16, 16, 16, float> acc[2][NF];
#pragma unroll
    for (int m = 0; m < 2; m++)
#pragma unroll
        for (int f = 0; f < NF; f++) wmma::fill_fragment(acc[m][f], 0.0f);

    const int arow = tid >> 1;            // 0..127
    const int akq  = (tid & 1) * 16;      // 0 or 16

    for (int kc = 0; kc < 128; kc += KCH) {
        // ---- stage A chunk: pure vector copies (rows < NPAD always valid) ----
        {
            size_t gsrc = (size_t)(rowBase + arow) * 128 + kc + akq;
            const uint4* sh = (const uint4*)(ahi + gsrc);
            const uint4* sl = (const uint4*)(alo + gsrc);
            uint4* dh = (uint4*)(Ahi + arow * KP + akq);
            uint4* dl = (uint4*)(Alo + arow * KP + akq);
            dh[0] = sh[0]; dh[1] = sh[1];
            dl[0] = sl[0]; dl[1] = sl[1];
        }
        // ---- stage W chunk: pure vector copies ----
#pragma unroll
        for (int f = tid; f < KCH * (COLT / 8); f += 256) {
            int k = f / (COLT / 8);
            int n = (f % (COLT / 8)) * 8;
            size_t gsrc = (size_t)(kc + k) * COLT + n;
            *(uint4*)(Whi + k * CP + n) = *(const uint4*)(whi + gsrc);
            *(uint4*)(Wlo + k * CP + n) = *(const uint4*)(wlo + gsrc);
        }
        __syncthreads();

#pragma unroll
        for (int kk = 0; kk < KCH; kk += 16) {
            wmma::fragment<wmma::matrix_a, 16, 16, 16, __nv_bfloat16,
                           wmma::row_major> ah0, ah1, al0, al1;
            wmma::load_matrix_sync(ah0, Ahi + (wm * 32) * KP + kk, KP);
            wmma::load_matrix_sync(ah1, Ahi + (wm * 32 + 16) * KP + kk, KP);
            wmma::load_matrix_sync(al0, Alo + (wm * 32) * KP + kk, KP);
            wmma::load_matrix_sync(al1, Alo + (wm * 32 + 16) * KP + kk, KP);
#pragma unroll
            for (int f = 0; f < NF; f++) {
                wmma::fragment<wmma::matrix_b, 16, 16, 16, __nv_bfloat16,
                               wmma::row_major> bh, bl;
                int ncol = wn * (COLT / 2) + f * 16;
                wmma::load_matrix_sync(bh, Whi + kk * CP + ncol, CP);
                wmma::load_matrix_sync(bl, Wlo + kk * CP + ncol, CP);
                wmma::mma_sync(acc[0][f], ah0, bh, acc[0][f]);
                wmma::mma_sync(acc[1][f], ah1, bh, acc[1][f]);
                wmma::mma_sync(acc[0][f], ah0, bl, acc[0][f]);
                wmma::mma_sync(acc[1][f], ah1, bl, acc[1][f]);
                wmma::mma_sync(acc[0][f], al0, bh, acc[0][f]);
                wmma::mma_sync(acc[1][f], al1, bh, acc[1][f]);
            }
        }
        __syncthreads();
    }

#pragma unroll
    for (int m = 0; m < 2; m++) {
        int r = rowBase + wm * 32 + m * 16;
#pragma unroll
        for (int f = 0; f < NF; f++) {
            int c = wn * (COLT / 2) + f * 16;
            wmma::store_matrix_sync(Cout + (size_t)r * COLT + c, acc[m][f],
                                    COLT, wmma::mem_row_major);
        }
    }
}

// ---------------- aggregation + combine --------------------------------------
// D==128 (hidden): writes bf16 hi/lo splits to g_ahi/g_alo (next GEMM's input).
// D==64 (final):   writes fp32 to outp.
template <int D, bool RELU>
__global__ __launch_bounds__(256)
void combine_kernel(const float* __restrict__ bias, float* __restrict__ outp) {
    int gw = (blockIdx.x * blockDim.x + threadIdx.x) >> 5;
    int lane = threadIdx.x & 31;
    if (gw >= NN) return;

    int beg = g_rowoff[gw];
    int end = g_rowoff[gw + 1];

    if (D == 128) {
        float4 acc = make_float4(0.f, 0.f, 0.f, 0.f);
        const float* t = g_t;
        int j = beg;
        for (; j + 4 <= end; j += 4) {
            int s0 = g_csr[j], s1 = g_csr[j + 1], s2 = g_csr[j + 2], s3 = g_csr[j + 3];
            float4 v0 = *(const float4*)(t + (size_t)s0 * 128 + lane * 4);
            float4 v1 = *(const float4*)(t + (size_t)s1 * 128 + lane * 4);
            float4 v2 = *(const float4*)(t + (size_t)s2 * 128 + lane * 4);
            float4 v3 = *(const float4*)(t + (size_t)s3 * 128 + lane * 4);
            acc.x += v0.x + v1.x + v2.x + v3.x;
            acc.y += v0.y + v1.y + v2.y + v3.y;
            acc.z += v0.z + v1.z + v2.z + v3.z;
            acc.w += v0.w + v1.w + v2.w + v3.w;
        }
        for (; j < end; j++) {
            int s = g_csr[j];
            float4 v = *(const float4*)(t + (size_t)s * 128 + lane * 4);
            acc.x += v.x; acc.y += v.y; acc.z += v.z; acc.w += v.w;
        }
        float inv = g_invdeg[gw];
        float4 rr = *(const float4*)(g_r + (size_t)gw * 128 + lane * 4);
        float o[4];
        o[0] = acc.x * inv + bias[lane * 4 + 0] + rr.x;
        o[1] = acc.y * inv + bias[lane * 4 + 1] + rr.y;
        o[2] = acc.z * inv + bias[lane * 4 + 2] + rr.z;
        o[3] = acc.w * inv + bias[lane * 4 + 3] + rr.w;
        __nv_bfloat16 h[4], l[4];
#pragma unroll
        for (int e = 0; e < 4; e++) {
            float v = RELU ? fmaxf(o[e], 0.f) : o[e];
            split_bf16(v, h[e], l[e]);
        }
        size_t dst = (size_t)gw * 128 + lane * 4;
        *(uint2*)(g_ahi + dst) = *(uint2*)h;
        *(uint2*)(g_alo + dst) = *(uint2*)l;
    } else {
        float2 acc = make_float2(0.f, 0.f);
        const float* t = g_t;
        int j = beg;
        for (; j + 4 <= end; j += 4) {
            int s0 = g_csr[j], s1 = g_csr[j + 1], s2 = g_csr[j + 2], s3 = g_csr[j + 3];
            float2 v0 = *(const float2*)(t + (size_t)s0 * 64 + lane * 2);
            float2 v1 = *(const float2*)(t + (size_t)s1 * 64 + lane * 2);
            float2 v2 = *(const float2*)(t + (size_t)s2 * 64 + lane * 2);
            float2 v3 = *(const float2*)(t + (size_t)s3 * 64 + lane * 2);
            acc.x += v0.x + v1.x + v2.x + v3.x;
            acc.y += v0.y + v1.y + v2.y + v3.y;
        }
        for (; j < end; j++) {
            int s = g_csr[j];
            float2 v = *(const float2*)(t + (size_t)s * 64 + lane * 2);
            acc.x += v.x; acc.y += v.y;
        }
        float inv = g_invdeg[gw];
        float2 rr = *(const float2*)(g_r + (size_t)gw * 64 + lane * 2);
        float2 o;
        o.x = acc.x * inv + bias[lane * 2 + 0] + rr.x;
        o.y = acc.y * inv + bias[lane * 2 + 1] + rr.y;
        if (RELU) { o.x = fmaxf(o.x, 0.f); o.y = fmaxf(o.y, 0.f); }
        *(float2*)(outp + (size_t)gw * 64 + lane * 2) = o;
    }
}

// ---------------- launch --------------------------------------------------------
extern "C" void kernel_launch(void* const* d_in, const int* in_sizes, int n_in,
                              void* d_out, int out_size) {
    const float* x    = (const float*)d_in[0];
    const void*  ei   = d_in[1];
    const float* w_l0 = (const float*)d_in[2];
    const float* b0   = (const float*)d_in[3];
    const float* w_r0 = (const float*)d_in[4];
    const float* w_l1 = (const float*)d_in[5];
    const float* b1   = (const float*)d_in[6];
    const float* w_r1 = (const float*)d_in[7];
    const float* w_l2 = (const float*)d_in[8];
    const float* b2   = (const float*)d_in[9];
    const float* w_r2 = (const float*)d_in[10];
    float* outp = (float*)d_out;

    const int gemmBlocks = (NN + 127) / 128;      // 391
    const int combBlocks = (NN * 32 + 255) / 256; // 6250

    // splits first, then prep; gemm layer-0 kept at launch #4 (ncu slot)
    split_x_kernel<<<(NN * 32 + 255) / 256, 256>>>(x);
    split_w_kernel<<<(WTOTAL + 255) / 256, 256>>>(w_l0, w_r0, w_l1, w_r1, w_l2, w_r2);
    count_deg_kernel<<<(EE + 255) / 256, 256>>>(ei);
    gemm_wmma_kernel<128><<<dim3(gemmBlocks, 2), 256>>>(1, WOFF0);
    blocksum_kernel<<<NBLK, 256>>>();
    scan_bsum_kernel<<<1, 256>>>();
    write_off_kernel<<<NBLK, 256>>>();
    fill_csr_kernel<<<(EE + 255) / 256, 256>>>(ei);
    combine_kernel<128, true><<<combBlocks, 256>>>(b0, nullptr);
    gemm_wmma_kernel<128><<<dim3(gemmBlocks, 2), 256>>>(0, WOFF1);
    combine_kernel<128, true><<<combBlocks, 256>>>(b1, nullptr);
    gemm_wmma_kernel<64><<<dim3(gemmBlocks, 2), 256>>>(0, WOFF2);
    combine_kernel<64, false><<<combBlocks, 256>>>(b2, outp);
}

// round 12
// speedup vs baseline: 1.0651x; 1.0175x over previous
#include <cuda_runtime.h>
#include <cuda_bf16.h>
#include <mma.h>
#include <stdint.h>

using namespace nvcuda;

#define NN  50000
#define EE  800000
#define NBLK 196            // ceil(NN/256)
#define NPAD (NN + 128)     // row padding: wmma stores / unguarded A reads stay in-bounds

// W split storage offsets (bf16 elements): layer0 128x128, layer1 128x128, layer2 128x64
#define WOFF0 0
#define WOFF1 16384
#define WOFF2 32768
#define WTOTAL 40960

// ---------------- scratch (device globals, zero-init at load) ---------------
__device__ __align__(16) float g_t[NPAD * 128];
__device__ __align__(16) float g_r[NPAD * 128];
__device__ __align__(16) __nv_bfloat16 g_xhi[NPAD * 128];  // split of x
__device__ __align__(16) __nv_bfloat16 g_xlo[NPAD * 128];
__device__ __align__(16) __nv_bfloat16 g_ahi[NPAD * 128];  // split of activations
__device__ __align__(16) __nv_bfloat16 g_alo[NPAD * 128];
__device__ __align__(16) __nv_bfloat16 g_whl_hi[WTOTAL];   // Wl splits, all layers
__device__ __align__(16) __nv_bfloat16 g_whl_lo[WTOTAL];
__device__ __align__(16) __nv_bfloat16 g_whr_hi[WTOTAL];   // Wr splits
__device__ __align__(16) __nv_bfloat16 g_whr_lo[WTOTAL];
__device__ int   g_degc[NN];
__device__ int   g_rowoff[NN + 1];
__device__ int   g_wptr[NN];
__device__ int   g_csr[EE];
__device__ float g_invdeg[NN];
__device__ int   g_bsum[NBLK];
__device__ int   g_bpre[NBLK];

// ---------------- bf16 split helper ------------------------------------------
__device__ __forceinline__ void split_bf16(float v, __nv_bfloat16& h, __nv_bfloat16& l) {
    h = __float2bfloat16(v);
    l = __float2bfloat16(v - __bfloat162float(h));
}

// ---------------- edge dtype probe --------------------------------------------
__device__ __forceinline__ int probe_is64(const void* ei) {
    int lane = threadIdx.x & 31;
    long long v = ((const long long*)ei)[lane];
    unsigned ok = __ballot_sync(0xffffffffu, v >= 0 && v < NN);
    return ok == 0xffffffffu;
}

__device__ __forceinline__ void load_edge(const void* ei, int e, int is64,
                                          int& s, int& d) {
    if (is64) {
        const long long* p = (const long long*)ei;
        s = (int)p[e];
        d = (int)p[EE + e];
    } else {
        const int* p = (const int*)ei;
        s = p[e];
        d = p[EE + e];
    }
    s = min(max(s, 0), NN - 1);
    d = min(max(d, 0), NN - 1);
}

// ---------------- one-time-per-launch splits ---------------------------------
__global__ void split_x_kernel(const float* __restrict__ x) {
    int i = blockIdx.x * blockDim.x + threadIdx.x;   // float4 index
    if (i >= NN * 32) return;
    float4 v = ((const float4*)x)[i];
    __nv_bfloat16 h[4], l[4];
    split_bf16(v.x, h[0], l[0]); split_bf16(v.y, h[1], l[1]);
    split_bf16(v.z, h[2], l[2]); split_bf16(v.w, h[3], l[3]);
    *(uint2*)(g_xhi + (size_t)i * 4) = *(uint2*)h;
    *(uint2*)(g_xlo + (size_t)i * 4) = *(uint2*)l;
}

__global__ void split_w_kernel(const float* __restrict__ wl0, const float* __restrict__ wr0,
                               const float* __restrict__ wl1, const float* __restrict__ wr1,
                               const float* __restrict__ wl2, const float* __restrict__ wr2) {
    int idx = blockIdx.x * blockDim.x + threadIdx.x;
    if (idx >= WTOTAL) return;
    const float *wl, *wr;
    int local;
    if (idx < WOFF1)      { wl = wl0; wr = wr0; local = idx; }
    else if (idx < WOFF2) { wl = wl1; wr = wr1; local = idx - WOFF1; }
    else                  { wl = wl2; wr = wr2; local = idx - WOFF2; }
    __nv_bfloat16 h, l;
    split_bf16(wl[local], h, l);
    g_whl_hi[idx] = h; g_whl_lo[idx] = l;
    split_bf16(wr[local], h, l);
    g_whr_hi[idx] = h; g_whr_lo[idx] = l;
}

// ---------------- graph preprocessing -----------------------------------------
__global__ void count_deg_kernel(const void* __restrict__ ei) {
    int is64 = probe_is64(ei);
    int e = blockIdx.x * blockDim.x + threadIdx.x;
    if (e < EE) {
        int s, d;
        load_edge(ei, e, is64, s, d);
        atomicAdd(&g_degc[d], 1);
    }
}

__global__ void blocksum_kernel() {
    int i = blockIdx.x * 256 + threadIdx.x;
    int v = (i < NN) ? g_degc[i] : 0;
#pragma unroll
    for (int off = 16; off > 0; off >>= 1)
        v += __shfl_down_sync(0xffffffffu, v, off);
    __shared__ int ws[8];
    if ((threadIdx.x & 31) == 0) ws[threadIdx.x >> 5] = v;
    __syncthreads();
    if (threadIdx.x == 0) {
        int s = 0;
#pragma unroll
        for (int w = 0; w < 8; w++) s += ws[w];
        g_bsum[blockIdx.x] = s;
    }
}

__global__ void scan_bsum_kernel() {
    __shared__ int sh[256];
    int t = threadIdx.x;
    int v = (t < NBLK) ? g_bsum[t] : 0;
    sh[t] = v;
    __syncthreads();
#pragma unroll
    for (int off = 1; off < 256; off <<= 1) {
        int u = (t >= off) ? sh[t - off] : 0;
        __syncthreads();
        sh[t] += u;
        __syncthreads();
    }
    if (t < NBLK) g_bpre[t] = sh[t] - v;
    if (t == NBLK - 1) g_rowoff[NN] = sh[t];
}

__global__ void write_off_kernel() {
    __shared__ int sh[256];
    int t = threadIdx.x;
    int i = blockIdx.x * 256 + t;
    int v = (i < NN) ? g_degc[i] : 0;
    sh[t] = v;
    __syncthreads();
#pragma unroll
    for (int off = 1; off < 256; off <<= 1) {
        int u = (t >= off) ? sh[t - off] : 0;
        __syncthreads();
        sh[t] += u;
        __syncthreads();
    }
    if (i < NN) {
        int excl = g_bpre[blockIdx.x] + sh[t] - v;
        g_rowoff[i] = excl;
        g_wptr[i]   = excl;
        g_invdeg[i] = 1.0f / fmaxf((float)v, 1.0f);
        g_degc[i]   = 0;
    }
}

__global__ void fill_csr_kernel(const void* __restrict__ ei) {
    int is64 = probe_is64(ei);
    int e = blockIdx.x * blockDim.x + threadIdx.x;
    if (e < EE) {
        int s, d;
        load_edge(ei, e, is64, s, d);
        int p = atomicAdd(&g_wptr[d], 1);
        if (p >= 0 && p < EE) g_csr[p] = s;
    }
}

// ---------------- fused dual wmma GEMM: t = A@Wl AND r = A@Wr ----------------
// CTA: 64 rows x (Wl||Wr) cols, 256 threads, 8 warps in 2m x 4n.
// Warp tile 32m x (WTOT/4)n -- SAME per-warp shape as the round-11 best, but
// A is staged once for BOTH outputs (halves A global+smem traffic, the 58% L1
// pipe). KCH=32 (same sync count), launch_bounds(256,2) (2 CTAs/SM).
#define KCH 32
#define KP  40     // A smem row stride (bf16 elems)

template <int COLT>   // 128 or 64; fused width = 2*COLT
__global__ __launch_bounds__(256, 2)
void gemm_wmma_kernel(int useX, int wOff) {
    constexpr int WTOT = 2 * COLT;      // 256 or 128
    constexpr int CP = WTOT + 8;        // W smem stride
    constexpr int WN = WTOT / 4;        // cols per warp (64 or 32)
    constexpr int NF = WN / 16;         // 16-col frags per warp (4 or 2)

    __shared__ __align__(16) __nv_bfloat16 Ahi[64 * KP];    //  5.1 KB
    __shared__ __align__(16) __nv_bfloat16 Alo[64 * KP];    //  5.1 KB
    __shared__ __align__(16) __nv_bfloat16 Whi[KCH * CP];   // 16.9 / 8.6 KB
    __shared__ __align__(16) __nv_bfloat16 Wlo[KCH * CP];   // 16.9 / 8.6 KB

    const __nv_bfloat16* ahi = useX ? g_xhi : g_ahi;
    const __nv_bfloat16* alo = useX ? g_xlo : g_alo;
    const __nv_bfloat16* wlh = g_whl_hi + wOff;
    const __nv_bfloat16* wll = g_whl_lo + wOff;
    const __nv_bfloat16* wrh = g_whr_hi + wOff;
    const __nv_bfloat16* wrl = g_whr_lo + wOff;

    const int tid = threadIdx.x;
    const int wid = tid >> 5;
    const int wm = wid & 1;           // m-tile 0..1 (32 rows each)
    const int wn = wid >> 1;          // n-tile 0..3 (WN cols each)
    const int rowBase = blockIdx.x * 64;

    wmma::fragment<wmma::accumulator, 16, 16, 16, float> acc[2][NF];
#pragma unroll
    for (int m = 0; m < 2; m++)
#pragma unroll
        for (int f = 0; f < NF; f++) wmma::fill_fragment(acc[m][f], 0.0f);

    const int arow = tid >> 2;            // 0..63
    const int akq  = (tid & 3) * 8;       // k offset 0,8,16,24 (uint4 = 8 bf16)

    for (int kc = 0; kc < 128; kc += KCH) {
        // ---- stage A chunk: 64 rows x 32 k, pure uint4 copies ----
        {
            size_t gsrc = (size_t)(rowBase + arow) * 128 + kc + akq;
            *(uint4*)(Ahi + arow * KP + akq) = *(const uint4*)(ahi + gsrc);
            *(uint4*)(Alo + arow * KP + akq) = *(const uint4*)(alo + gsrc);
        }
        // ---- stage W chunk: 32 k x (Wl||Wr), pure uint4 copies ----
#pragma unroll
        for (int f = tid; f < KCH * (WTOT / 8); f += 256) {
            int k = f / (WTOT / 8);
            int n = (f % (WTOT / 8)) * 8;
            const __nv_bfloat16* sh = (n < COLT) ? (wlh + (size_t)(kc + k) * COLT + n)
                                                 : (wrh + (size_t)(kc + k) * COLT + (n - COLT));
            const __nv_bfloat16* sl = (n < COLT) ? (wll + (size_t)(kc + k) * COLT + n)
                                                 : (wrl + (size_t)(kc + k) * COLT + (n - COLT));
            *(uint4*)(Whi + k * CP + n) = *(const uint4*)sh;
            *(uint4*)(Wlo + k * CP + n) = *(const uint4*)sl;
        }
        __syncthreads();

#pragma unroll
        for (int kk = 0; kk < KCH; kk += 16) {
            wmma::fragment<wmma::matrix_a, 16, 16, 16, __nv_bfloat16,
                           wmma::row_major> ah0, ah1, al0, al1;
            wmma::load_matrix_sync(ah0, Ahi + (wm * 32) * KP + kk, KP);
            wmma::load_matrix_sync(ah1, Ahi + (wm * 32 + 16) * KP + kk, KP);
            wmma::load_matrix_sync(al0, Alo + (wm * 32) * KP + kk, KP);
            wmma::load_matrix_sync(al1, Alo + (wm * 32 + 16) * KP + kk, KP);
#pragma unroll
            for (int f = 0; f < NF; f++) {
                wmma::fragment<wmma::matrix_b, 16, 16, 16, __nv_bfloat16,
                               wmma::row_major> bh, bl;
                int ncol = wn * WN + f * 16;
                wmma::load_matrix_sync(bh, Whi + kk * CP + ncol, CP);
                wmma::load_matrix_sync(bl, Wlo + kk * CP + ncol, CP);
                wmma::mma_sync(acc[0][f], ah0, bh, acc[0][f]);
                wmma::mma_sync(acc[1][f], ah1, bh, acc[1][f]);
                wmma::mma_sync(acc[0][f], ah0, bl, acc[0][f]);
                wmma::mma_sync(acc[1][f], ah1, bl, acc[1][f]);
                wmma::mma_sync(acc[0][f], al0, bh, acc[0][f]);
                wmma::mma_sync(acc[1][f], al1, bh, acc[1][f]);
            }
        }
        __syncthreads();
    }

    // ---- epilogue: cols [0,COLT) -> g_t, [COLT,WTOT) -> g_r ----
#pragma unroll
    for (int m = 0; m < 2; m++) {
        int r = rowBase + wm * 32 + m * 16;
#pragma unroll
        for (int f = 0; f < NF; f++) {
            int ncol = wn * WN + f * 16;
            float* Cout = (ncol < COLT) ? (g_t + (size_t)r * COLT + ncol)
                                        : (g_r + (size_t)r * COLT + (ncol - COLT));
            wmma::store_matrix_sync(Cout, acc[m][f], COLT, wmma::mem_row_major);
        }
    }
}

// ---------------- aggregation + combine --------------------------------------
// D==128 (hidden): writes bf16 hi/lo splits to g_ahi/g_alo (next GEMM's input).
// D==64 (final):   writes fp32 to outp.
template <int D, bool RELU>
__global__ __launch_bounds__(256)
void combine_kernel(const float* __restrict__ bias, float* __restrict__ outp) {
    int gw = (blockIdx.x * blockDim.x + threadIdx.x) >> 5;
    int lane = threadIdx.x & 31;
    if (gw >= NN) return;

    int beg = g_rowoff[gw];
    int end = g_rowoff[gw + 1];

    if (D == 128) {
        float4 acc = make_float4(0.f, 0.f, 0.f, 0.f);
        const float* t = g_t;
        int j = beg;
        for (; j + 4 <= end; j += 4) {
            int s0 = g_csr[j], s1 = g_csr[j + 1], s2 = g_csr[j + 2], s3 = g_csr[j + 3];
            float4 v0 = *(const float4*)(t + (size_t)s0 * 128 + lane * 4);
            float4 v1 = *(const float4*)(t + (size_t)s1 * 128 + lane * 4);
            float4 v2 = *(const float4*)(t + (size_t)s2 * 128 + lane * 4);
            float4 v3 = *(const float4*)(t + (size_t)s3 * 128 + lane * 4);
            acc.x += v0.x + v1.x + v2.x + v3.x;
            acc.y += v0.y + v1.y + v2.y + v3.y;
            acc.z += v0.z + v1.z + v2.z + v3.z;
            acc.w += v0.w + v1.w + v2.w + v3.w;
        }
        for (; j < end; j++) {
            int s = g_csr[j];
            float4 v = *(const float4*)(t + (size_t)s * 128 + lane * 4);
            acc.x += v.x; acc.y += v.y; acc.z += v.z; acc.w += v.w;
        }
        float inv = g_invdeg[gw];
        float4 rr = *(const float4*)(g_r + (size_t)gw * 128 + lane * 4);
        float o[4];
        o[0] = acc.x * inv + bias[lane * 4 + 0] + rr.x;
        o[1] = acc.y * inv + bias[lane * 4 + 1] + rr.y;
        o[2] = acc.z * inv + bias[lane * 4 + 2] + rr.z;
        o[3] = acc.w * inv + bias[lane * 4 + 3] + rr.w;
        __nv_bfloat16 h[4], l[4];
#pragma unroll
        for (int e = 0; e < 4; e++) {
            float v = RELU ? fmaxf(o[e], 0.f) : o[e];
            split_bf16(v, h[e], l[e]);
        }
        size_t dst = (size_t)gw * 128 + lane * 4;
        *(uint2*)(g_ahi + dst) = *(uint2*)h;
        *(uint2*)(g_alo + dst) = *(uint2*)l;
    } else {
        float2 acc = make_float2(0.f, 0.f);
        const float* t = g_t;
        int j = beg;
        for (; j + 4 <= end; j += 4) {
            int s0 = g_csr[j], s1 = g_csr[j + 1], s2 = g_csr[j + 2], s3 = g_csr[j + 3];
            float2 v0 = *(const float2*)(t + (size_t)s0 * 64 + lane * 2);
            float2 v1 = *(const float2*)(t + (size_t)s1 * 64 + lane * 2);
            float2 v2 = *(const float2*)(t + (size_t)s2 * 64 + lane * 2);
            float2 v3 = *(const float2*)(t + (size_t)s3 * 64 + lane * 2);
            acc.x += v0.x + v1.x + v2.x + v3.x;
            acc.y += v0.y + v1.y + v2.y + v3.y;
        }
        for (; j < end; j++) {
            int s = g_csr[j];
            float2 v = *(const float2*)(t + (size_t)s * 64 + lane * 2);
            acc.x += v.x; acc.y += v.y;
        }
        float inv = g_invdeg[gw];
        float2 rr = *(const float2*)(g_r + (size_t)gw * 64 + lane * 2);
        float2 o;
        o.x = acc.x * inv + bias[lane * 2 + 0] + rr.x;
        o.y = acc.y * inv + bias[lane * 2 + 1] + rr.y;
        if (RELU) { o.x = fmaxf(o.x, 0.f); o.y = fmaxf(o.y, 0.f); }
        *(float2*)(outp + (size_t)gw * 64 + lane * 2) = o;
    }
}

// ---------------- launch --------------------------------------------------------
extern "C" void kernel_launch(void* const* d_in, const int* in_sizes, int n_in,
                              void* d_out, int out_size) {
    const float* x    = (const float*)d_in[0];
    const void*  ei   = d_in[1];
    const float* w_l0 = (const float*)d_in[2];
    const float* b0   = (const float*)d_in[3];
    const float* w_r0 = (const float*)d_in[4];
    const float* w_l1 = (const float*)d_in[5];
    const float* b1   = (const float*)d_in[6];
    const float* w_r1 = (const float*)d_in[7];
    const float* w_l2 = (const float*)d_in[8];
    const float* b2   = (const float*)d_in[9];
    const float* w_r2 = (const float*)d_in[10];
    float* outp = (float*)d_out;

    const int gemmBlocks = (NN + 63) / 64;        // 782
    const int combBlocks = (NN * 32 + 255) / 256; // 6250

    split_x_kernel<<<(NN * 32 + 255) / 256, 256>>>(x);
    split_w_kernel<<<(WTOTAL + 255) / 256, 256>>>(w_l0, w_r0, w_l1, w_r1, w_l2, w_r2);
    count_deg_kernel<<<(EE + 255) / 256, 256>>>(ei);
    gemm_wmma_kernel<128><<<gemmBlocks, 256>>>(1, WOFF0);
    blocksum_kernel<<<NBLK, 256>>>();
    scan_bsum_kernel<<<1, 256>>>();
    write_off_kernel<<<NBLK, 256>>>();
    fill_csr_kernel<<<(EE + 255) / 256, 256>>>(ei);
    combine_kernel<128, true><<<combBlocks, 256>>>(b0, nullptr);
    gemm_wmma_kernel<128><<<gemmBlocks, 256>>>(0, WOFF1);
    combine_kernel<128, true><<<combBlocks, 256>>>(b1, nullptr);
    gemm_wmma_kernel<64><<<gemmBlocks, 256>>>(0, WOFF2);
    combine_kernel<64, false><<<combBlocks, 256>>>(b2, outp);
}

// round 13
// speedup vs baseline: 1.3621x; 1.2789x over previous
#include <cuda_runtime.h>
#include <cuda_fp16.h>
#include <cuda_bf16.h>
#include <mma.h>
#include <stdint.h>

using namespace nvcuda;

#define NN  50000
#define EE  800000
#define NBLK 196            // ceil(NN/256)
#define NPAD (NN + 128)     // row padding: wmma stores / unguarded A reads stay in-bounds

// W split storage offsets (fp16 elements): layer0 128x128, layer1 128x128, layer2 128x64
#define WOFF0 0
#define WOFF1 16384
#define WOFF2 32768
#define WTOTAL 40960

// ---------------- scratch (device globals, zero-init at load) ---------------
__device__ __align__(16) float g_t[NPAD * 128];
__device__ __align__(16) float g_r[NPAD * 128];
__device__ __align__(16) __half g_xh[NPAD * 128];   // fp16 of x
__device__ __align__(16) __half g_ah[NPAD * 128];   // fp16 of activations
__device__ __align__(16) __half g_wlh[WTOTAL];      // Wl hi, all layers
__device__ __align__(16) __half g_wll[WTOTAL];      // Wl lo
__device__ __align__(16) __half g_wrh[WTOTAL];      // Wr hi
__device__ __align__(16) __half g_wrl[WTOTAL];      // Wr lo
__device__ int   g_degc[NN];
__device__ int   g_rowoff[NN + 1];
__device__ int   g_wptr[NN];
__device__ int   g_csr[EE];
__device__ float g_invdeg[NN];
__device__ int   g_bsum[NBLK];
__device__ int   g_bpre[NBLK];

// ---------------- fp16 split helper ------------------------------------------
__device__ __forceinline__ void split_fp16(float v, __half& h, __half& l) {
    h = __float2half_rn(v);
    l = __float2half_rn(v - __half2float(h));
}

// ---------------- edge dtype probe --------------------------------------------
__device__ __forceinline__ int probe_is64(const void* ei) {
    int lane = threadIdx.x & 31;
    long long v = ((const long long*)ei)[lane];
    unsigned ok = __ballot_sync(0xffffffffu, v >= 0 && v < NN);
    return ok == 0xffffffffu;
}

__device__ __forceinline__ void load_edge(const void* ei, int e, int is64,
                                          int& s, int& d) {
    if (is64) {
        const long long* p = (const long long*)ei;
        s = (int)p[e];
        d = (int)p[EE + e];
    } else {
        const int* p = (const int*)ei;
        s = p[e];
        d = p[EE + e];
    }
    s = min(max(s, 0), NN - 1);
    d = min(max(d, 0), NN - 1);
}

// ---------------- one-time-per-launch conversions -----------------------------
__global__ void split_x_kernel(const float* __restrict__ x) {
    int i = blockIdx.x * blockDim.x + threadIdx.x;   // float4 index
    if (i >= NN * 32) return;
    float4 v = ((const float4*)x)[i];
    __half h[4];
    h[0] = __float2half_rn(v.x); h[1] = __float2half_rn(v.y);
    h[2] = __float2half_rn(v.z); h[3] = __float2half_rn(v.w);
    *(uint2*)(g_xh + (size_t)i * 4) = *(uint2*)h;
}

__global__ void split_w_kernel(const float* __restrict__ wl0, const float* __restrict__ wr0,
                               const float* __restrict__ wl1, const float* __restrict__ wr1,
                               const float* __restrict__ wl2, const float* __restrict__ wr2) {
    int idx = blockIdx.x * blockDim.x + threadIdx.x;
    if (idx >= WTOTAL) return;
    const float *wl, *wr;
    int local;
    if (idx < WOFF1)      { wl = wl0; wr = wr0; local = idx; }
    else if (idx < WOFF2) { wl = wl1; wr = wr1; local = idx - WOFF1; }
    else                  { wl = wl2; wr = wr2; local = idx - WOFF2; }
    __half h, l;
    split_fp16(wl[local], h, l);
    g_wlh[idx] = h; g_wll[idx] = l;
    split_fp16(wr[local], h, l);
    g_wrh[idx] = h; g_wrl[idx] = l;
}

// ---------------- graph preprocessing -----------------------------------------
__global__ void count_deg_kernel(const void* __restrict__ ei) {
    int is64 = probe_is64(ei);
    int e = blockIdx.x * blockDim.x + threadIdx.x;
    if (e < EE) {
        int s, d;
        load_edge(ei, e, is64, s, d);
        atomicAdd(&g_degc[d], 1);
    }
}

__global__ void blocksum_kernel() {
    int i = blockIdx.x * 256 + threadIdx.x;
    int v = (i < NN) ? g_degc[i] : 0;
#pragma unroll
    for (int off = 16; off > 0; off >>= 1)
        v += __shfl_down_sync(0xffffffffu, v, off);
    __shared__ int ws[8];
    if ((threadIdx.x & 31) == 0) ws[threadIdx.x >> 5] = v;
    __syncthreads();
    if (threadIdx.x == 0) {
        int s = 0;
#pragma unroll
        for (int w = 0; w < 8; w++) s += ws[w];
        g_bsum[blockIdx.x] = s;
    }
}

__global__ void scan_bsum_kernel() {
    __shared__ int sh[256];
    int t = threadIdx.x;
    int v = (t < NBLK) ? g_bsum[t] : 0;
    sh[t] = v;
    __syncthreads();
#pragma unroll
    for (int off = 1; off < 256; off <<= 1) {
        int u = (t >= off) ? sh[t - off] : 0;
        __syncthreads();
        sh[t] += u;
        __syncthreads();
    }
    if (t < NBLK) g_bpre[t] = sh[t] - v;
    if (t == NBLK - 1) g_rowoff[NN] = sh[t];
}

__global__ void write_off_kernel() {
    __shared__ int sh[256];
    int t = threadIdx.x;
    int i = blockIdx.x * 256 + t;
    int v = (i < NN) ? g_degc[i] : 0;
    sh[t] = v;
    __syncthreads();
#pragma unroll
    for (int off = 1; off < 256; off <<= 1) {
        int u = (t >= off) ? sh[t - off] : 0;
        __syncthreads();
        sh[t] += u;
        __syncthreads();
    }
    if (i < NN) {
        int excl = g_bpre[blockIdx.x] + sh[t] - v;
        g_rowoff[i] = excl;
        g_wptr[i]   = excl;
        g_invdeg[i] = 1.0f / fmaxf((float)v, 1.0f);
        g_degc[i]   = 0;
    }
}

__global__ void fill_csr_kernel(const void* __restrict__ ei) {
    int is64 = probe_is64(ei);
    int e = blockIdx.x * blockDim.x + threadIdx.x;
    if (e < EE) {
        int s, d;
        load_edge(ei, e, is64, s, d);
        int p = atomicAdd(&g_wptr[d], 1);
        if (p >= 0 && p < EE) g_csr[p] = s;
    }
}

// ---------------- fused dual wmma GEMM: t = A@Wl AND r = A@Wr ----------------
// fp16 2-term split: D = A * Whi + A * Wlo, fp32 accumulators.
// A single fp16 (11-bit mantissa), W = hi + lo fp16 (~20 effective bits).
// Dropped term lo_a*w ~ 2^-12 relative -> final rel_err ~3e-4 (<< 1e-3).
// CTA: 64 rows x (Wl||Wr), 256 threads, 8 warps 2m x 4n; 2 CTAs/SM pinned.
#define KCH 32
#define KP  40     // A smem row stride (fp16 elems)

template <int COLT>   // 128 or 64; fused width = 2*COLT
__global__ __launch_bounds__(256, 2)
void gemm_wmma_kernel(int useX, int wOff) {
    constexpr int WTOT = 2 * COLT;      // 256 or 128
    constexpr int CP = WTOT + 8;        // W smem stride
    constexpr int WN = WTOT / 4;        // cols per warp (64 or 32)
    constexpr int NF = WN / 16;         // 16-col frags per warp (4 or 2)

    __shared__ __align__(16) __half Ah[64 * KP];     //  5.1 KB
    __shared__ __align__(16) __half Whi[KCH * CP];   // 16.9 / 8.7 KB
    __shared__ __align__(16) __half Wlo[KCH * CP];   // 16.9 / 8.7 KB

    const __half* ah  = useX ? g_xh : g_ah;
    const __half* wlh = g_wlh + wOff;
    const __half* wll = g_wll + wOff;
    const __half* wrh = g_wrh + wOff;
    const __half* wrl = g_wrl + wOff;

    const int tid = threadIdx.x;
    const int wid = tid >> 5;
    const int wm = wid & 1;           // m-tile 0..1 (32 rows each)
    const int wn = wid >> 1;          // n-tile 0..3 (WN cols each)
    const int rowBase = blockIdx.x * 64;

    wmma::fragment<wmma::accumulator, 16, 16, 16, float> acc[2][NF];
#pragma unroll
    for (int m = 0; m < 2; m++)
#pragma unroll
        for (int f = 0; f < NF; f++) wmma::fill_fragment(acc[m][f], 0.0f);

    const int arow = tid >> 2;            // 0..63
    const int akq  = (tid & 3) * 8;       // k offset 0,8,16,24 (uint4 = 8 fp16)

    for (int kc = 0; kc < 128; kc += KCH) {
        // ---- stage A chunk: 64 rows x 32 k, one uint4 per thread ----
        {
            size_t gsrc = (size_t)(rowBase + arow) * 128 + kc + akq;
            *(uint4*)(Ah + arow * KP + akq) = *(const uint4*)(ah + gsrc);
        }
        // ---- stage W chunk: 32 k x (Wl||Wr), pure uint4 copies ----
#pragma unroll
        for (int f = tid; f < KCH * (WTOT / 8); f += 256) {
            int k = f / (WTOT / 8);
            int n = (f % (WTOT / 8)) * 8;
            const __half* sh = (n < COLT) ? (wlh + (size_t)(kc + k) * COLT + n)
                                          : (wrh + (size_t)(kc + k) * COLT + (n - COLT));
            const __half* sl = (n < COLT) ? (wll + (size_t)(kc + k) * COLT + n)
                                          : (wrl + (size_t)(kc + k) * COLT + (n - COLT));
            *(uint4*)(Whi + k * CP + n) = *(const uint4*)sh;
            *(uint4*)(Wlo + k * CP + n) = *(const uint4*)sl;
        }
        __syncthreads();

#pragma unroll
        for (int kk = 0; kk < KCH; kk += 16) {
            wmma::fragment<wmma::matrix_a, 16, 16, 16, __half,
                           wmma::row_major> a0, a1;
            wmma::load_matrix_sync(a0, Ah + (wm * 32) * KP + kk, KP);
            wmma::load_matrix_sync(a1, Ah + (wm * 32 + 16) * KP + kk, KP);
#pragma unroll
            for (int f = 0; f < NF; f++) {
                wmma::fragment<wmma::matrix_b, 16, 16, 16, __half,
                               wmma::row_major> bh, bl;
                int ncol = wn * WN + f * 16;
                wmma::load_matrix_sync(bh, Whi + kk * CP + ncol, CP);
                wmma::load_matrix_sync(bl, Wlo + kk * CP + ncol, CP);
                wmma::mma_sync(acc[0][f], a0, bh, acc[0][f]);
                wmma::mma_sync(acc[1][f], a1, bh, acc[1][f]);
                wmma::mma_sync(acc[0][f], a0, bl, acc[0][f]);
                wmma::mma_sync(acc[1][f], a1, bl, acc[1][f]);
            }
        }
        __syncthreads();
    }

    // ---- epilogue: cols [0,COLT) -> g_t, [COLT,WTOT) -> g_r ----
#pragma unroll
    for (int m = 0; m < 2; m++) {
        int r = rowBase + wm * 32 + m * 16;
#pragma unroll
        for (int f = 0; f < NF; f++) {
            int ncol = wn * WN + f * 16;
            float* Cout = (ncol < COLT) ? (g_t + (size_t)r * COLT + ncol)
                                        : (g_r + (size_t)r * COLT + (ncol - COLT));
            wmma::store_matrix_sync(Cout, acc[m][f], COLT, wmma::mem_row_major);
        }
    }
}

// ---------------- aggregation + combine --------------------------------------
// D==128 (hidden): writes fp16 activations to g_ah (next GEMM's input).
// D==64 (final):   writes fp32 to outp.
template <int D, bool RELU>
__global__ __launch_bounds__(256)
void combine_kernel(const float* __restrict__ bias, float* __restrict__ outp) {
    int gw = (blockIdx.x * blockDim.x + threadIdx.x) >> 5;
    int lane = threadIdx.x & 31;
    if (gw >= NN) return;

    int beg = g_rowoff[gw];
    int end = g_rowoff[gw + 1];

    if (D == 128) {
        float4 acc = make_float4(0.f, 0.f, 0.f, 0.f);
        const float* t = g_t;
        int j = beg;
        for (; j + 4 <= end; j += 4) {
            int s0 = g_csr[j], s1 = g_csr[j + 1], s2 = g_csr[j + 2], s3 = g_csr[j + 3];
            float4 v0 = *(const float4*)(t + (size_t)s0 * 128 + lane * 4);
            float4 v1 = *(const float4*)(t + (size_t)s1 * 128 + lane * 4);
            float4 v2 = *(const float4*)(t + (size_t)s2 * 128 + lane * 4);
            float4 v3 = *(const float4*)(t + (size_t)s3 * 128 + lane * 4);
            acc.x += v0.x + v1.x + v2.x + v3.x;
            acc.y += v0.y + v1.y + v2.y + v3.y;
            acc.z += v0.z + v1.z + v2.z + v3.z;
            acc.w += v0.w + v1.w + v2.w + v3.w;
        }
        for (; j < end; j++) {
            int s = g_csr[j];
            float4 v = *(const float4*)(t + (size_t)s * 128 + lane * 4);
            acc.x += v.x; acc.y += v.y; acc.z += v.z; acc.w += v.w;
        }
        float inv = g_invdeg[gw];
        float4 rr = *(const float4*)(g_r + (size_t)gw * 128 + lane * 4);
        float o[4];
        o[0] = acc.x * inv + bias[lane * 4 + 0] + rr.x;
        o[1] = acc.y * inv + bias[lane * 4 + 1] + rr.y;
        o[2] = acc.z * inv + bias[lane * 4 + 2] + rr.z;
        o[3] = acc.w * inv + bias[lane * 4 + 3] + rr.w;
        __half h[4];
#pragma unroll
        for (int e = 0; e < 4; e++) {
            float v = RELU ? fmaxf(o[e], 0.f) : o[e];
            h[e] = __float2half_rn(v);
        }
        *(uint2*)(g_ah + (size_t)gw * 128 + lane * 4) = *(uint2*)h;
    } else {
        float2 acc = make_float2(0.f, 0.f);
        const float* t = g_t;
        int j = beg;
        for (; j + 4 <= end; j += 4) {
            int s0 = g_csr[j], s1 = g_csr[j + 1], s2 = g_csr[j + 2], s3 = g_csr[j + 3];
            float2 v0 = *(const float2*)(t + (size_t)s0 * 64 + lane * 2);
            float2 v1 = *(const float2*)(t + (size_t)s1 * 64 + lane * 2);
            float2 v2 = *(const float2*)(t + (size_t)s2 * 64 + lane * 2);
            float2 v3 = *(const float2*)(t + (size_t)s3 * 64 + lane * 2);
            acc.x += v0.x + v1.x + v2.x + v3.x;
            acc.y += v0.y + v1.y + v2.y + v3.y;
        }
        for (; j < end; j++) {
            int s = g_csr[j];
            float2 v = *(const float2*)(t + (size_t)s * 64 + lane * 2);
            acc.x += v.x; acc.y += v.y;
        }
        float inv = g_invdeg[gw];
        float2 rr = *(const float2*)(g_r + (size_t)gw * 64 + lane * 2);
        float2 o;
        o.x = acc.x * inv + bias[lane * 2 + 0] + rr.x;
        o.y = acc.y * inv + bias[lane * 2 + 1] + rr.y;
        if (RELU) { o.x = fmaxf(o.x, 0.f); o.y = fmaxf(o.y, 0.f); }
        *(float2*)(outp + (size_t)gw * 64 + lane * 2) = o;
    }
}

// ---------------- launch --------------------------------------------------------
extern "C" void kernel_launch(void* const* d_in, const int* in_sizes, int n_in,
                              void* d_out, int out_size) {
    const float* x    = (const float*)d_in[0];
    const void*  ei   = d_in[1];
    const float* w_l0 = (const float*)d_in[2];
    const float* b0   = (const float*)d_in[3];
    const float* w_r0 = (const float*)d_in[4];
    const float* w_l1 = (const float*)d_in[5];
    const float* b1   = (const float*)d_in[6];
    const float* w_r1 = (const float*)d_in[7];
    const float* w_l2 = (const float*)d_in[8];
    const float* b2   = (const float*)d_in[9];
    const float* w_r2 = (const float*)d_in[10];
    float* outp = (float*)d_out;

    const int gemmBlocks = (NN + 63) / 64;        // 782
    const int combBlocks = (NN * 32 + 255) / 256; // 6250

    split_x_kernel<<<(NN * 32 + 255) / 256, 256>>>(x);
    split_w_kernel<<<(WTOTAL + 255) / 256, 256>>>(w_l0, w_r0, w_l1, w_r1, w_l2, w_r2);
    count_deg_kernel<<<(EE + 255) / 256, 256>>>(ei);
    gemm_wmma_kernel<128><<<gemmBlocks, 256>>>(1, WOFF0);     // ncu slot
    blocksum_kernel<<<NBLK, 256>>>();
    scan_bsum_kernel<<<1, 256>>>();
    write_off_kernel<<<NBLK, 256>>>();
    fill_csr_kernel<<<(EE + 255) / 256, 256>>>(ei);
    combine_kernel<128, true><<<combBlocks, 256>>>(b0, nullptr);
    gemm_wmma_kernel<128><<<gemmBlocks, 256>>>(0, WOFF1);
    combine_kernel<128, true><<<combBlocks, 256>>>(b1, nullptr);
    gemm_wmma_kernel<64><<<gemmBlocks, 256>>>(0, WOFF2);
    combine_kernel<64, false><<<combBlocks, 256>>>(b2, outp);
}

// round 14
// speedup vs baseline: 1.4678x; 1.0775x over previous
#include <cuda_runtime.h>
#include <cuda_fp16.h>
#include <mma.h>
#include <stdint.h>

using namespace nvcuda;

#define NN  50000
#define EE  800000
#define NBLK 196            // ceil(NN/256)
#define NPAD (NN + 128)     // row padding: wmma stores / unguarded A reads stay in-bounds

// W split storage offsets (fp16 elements): layer0 128x128, layer1 128x128, layer2 128x64
#define WOFF0 0
#define WOFF1 16384
#define WOFF2 32768
#define WTOTAL 40960

// ---------------- scratch (device globals, zero-init at load) ---------------
__device__ __align__(16) __half g_th[NPAD * 128];   // t = h @ w_l, fp16 (gather operand)
__device__ __align__(16) float  g_r[NPAD * 128];    // r = h @ w_r, fp32
__device__ __align__(16) __half g_xh[NPAD * 128];   // fp16 of x
__device__ __align__(16) __half g_ah[NPAD * 128];   // fp16 of activations
__device__ __align__(16) __half g_wlh[WTOTAL];      // Wl hi, all layers
__device__ __align__(16) __half g_wll[WTOTAL];      // Wl lo
__device__ __align__(16) __half g_wrh[WTOTAL];      // Wr hi
__device__ __align__(16) __half g_wrl[WTOTAL];      // Wr lo
__device__ int   g_degc[NN];
__device__ int   g_rowoff[NN + 1];
__device__ int   g_wptr[NN];
__device__ int   g_csr[EE];
__device__ float g_invdeg[NN];
__device__ int   g_bsum[NBLK];
__device__ int   g_bpre[NBLK];

// ---------------- fp16 split helper ------------------------------------------
__device__ __forceinline__ void split_fp16(float v, __half& h, __half& l) {
    h = __float2half_rn(v);
    l = __float2half_rn(v - __half2float(h));
}

// ---------------- edge dtype probe --------------------------------------------
__device__ __forceinline__ int probe_is64(const void* ei) {
    int lane = threadIdx.x & 31;
    long long v = ((const long long*)ei)[lane];
    unsigned ok = __ballot_sync(0xffffffffu, v >= 0 && v < NN);
    return ok == 0xffffffffu;
}

__device__ __forceinline__ void load_edge(const void* ei, int e, int is64,
                                          int& s, int& d) {
    if (is64) {
        const long long* p = (const long long*)ei;
        s = (int)p[e];
        d = (int)p[EE + e];
    } else {
        const int* p = (const int*)ei;
        s = p[e];
        d = p[EE + e];
    }
    s = min(max(s, 0), NN - 1);
    d = min(max(d, 0), NN - 1);
}

// ---------------- one-time-per-launch conversions -----------------------------
__global__ void split_x_kernel(const float* __restrict__ x) {
    int i = blockIdx.x * blockDim.x + threadIdx.x;   // float4 index
    if (i >= NN * 32) return;
    float4 v = ((const float4*)x)[i];
    __half h[4];
    h[0] = __float2half_rn(v.x); h[1] = __float2half_rn(v.y);
    h[2] = __float2half_rn(v.z); h[3] = __float2half_rn(v.w);
    *(uint2*)(g_xh + (size_t)i * 4) = *(uint2*)h;
}

__global__ void split_w_kernel(const float* __restrict__ wl0, const float* __restrict__ wr0,
                               const float* __restrict__ wl1, const float* __restrict__ wr1,
                               const float* __restrict__ wl2, const float* __restrict__ wr2) {
    int idx = blockIdx.x * blockDim.x + threadIdx.x;
    if (idx >= WTOTAL) return;
    const float *wl, *wr;
    int local;
    if (idx < WOFF1)      { wl = wl0; wr = wr0; local = idx; }
    else if (idx < WOFF2) { wl = wl1; wr = wr1; local = idx - WOFF1; }
    else                  { wl = wl2; wr = wr2; local = idx - WOFF2; }
    __half h, l;
    split_fp16(wl[local], h, l);
    g_wlh[idx] = h; g_wll[idx] = l;
    split_fp16(wr[local], h, l);
    g_wrh[idx] = h; g_wrl[idx] = l;
}

// ---------------- graph preprocessing -----------------------------------------
__global__ void count_deg_kernel(const void* __restrict__ ei) {
    int is64 = probe_is64(ei);
    int e = blockIdx.x * blockDim.x + threadIdx.x;
    if (e < EE) {
        int s, d;
        load_edge(ei, e, is64, s, d);
        atomicAdd(&g_degc[d], 1);
    }
}

__global__ void blocksum_kernel() {
    int i = blockIdx.x * 256 + threadIdx.x;
    int v = (i < NN) ? g_degc[i] : 0;
#pragma unroll
    for (int off = 16; off > 0; off >>= 1)
        v += __shfl_down_sync(0xffffffffu, v, off);
    __shared__ int ws[8];
    if ((threadIdx.x & 31) == 0) ws[threadIdx.x >> 5] = v;
    __syncthreads();
    if (threadIdx.x == 0) {
        int s = 0;
#pragma unroll
        for (int w = 0; w < 8; w++) s += ws[w];
        g_bsum[blockIdx.x] = s;
    }
}

__global__ void scan_bsum_kernel() {
    __shared__ int sh[256];
    int t = threadIdx.x;
    int v = (t < NBLK) ? g_bsum[t] : 0;
    sh[t] = v;
    __syncthreads();
#pragma unroll
    for (int off = 1; off < 256; off <<= 1) {
        int u = (t >= off) ? sh[t - off] : 0;
        __syncthreads();
        sh[t] += u;
        __syncthreads();
    }
    if (t < NBLK) g_bpre[t] = sh[t] - v;
    if (t == NBLK - 1) g_rowoff[NN] = sh[t];
}

__global__ void write_off_kernel() {
    __shared__ int sh[256];
    int t = threadIdx.x;
    int i = blockIdx.x * 256 + t;
    int v = (i < NN) ? g_degc[i] : 0;
    sh[t] = v;
    __syncthreads();
#pragma unroll
    for (int off = 1; off < 256; off <<= 1) {
        int u = (t >= off) ? sh[t - off] : 0;
        __syncthreads();
        sh[t] += u;
        __syncthreads();
    }
    if (i < NN) {
        int excl = g_bpre[blockIdx.x] + sh[t] - v;
        g_rowoff[i] = excl;
        g_wptr[i]   = excl;
        g_invdeg[i] = 1.0f / fmaxf((float)v, 1.0f);
        g_degc[i]   = 0;
    }
}

__global__ void fill_csr_kernel(const void* __restrict__ ei) {
    int is64 = probe_is64(ei);
    int e = blockIdx.x * blockDim.x + threadIdx.x;
    if (e < EE) {
        int s, d;
        load_edge(ei, e, is64, s, d);
        int p = atomicAdd(&g_wptr[d], 1);
        if (p >= 0 && p < EE) g_csr[p] = s;
    }
}

// ---------------- fused dual wmma GEMM: t(fp16) = A@Wl, r(fp32) = A@Wr -------
// fp16 2-term split: D = A * Whi + A * Wlo, fp32 accumulators.
// CTA: 64 rows x (Wl||Wr), 256 threads, 8 warps 2m x 4n; 2 CTAs/SM pinned.
// t-half warps (wn<2) bounce their fp32 acc frags through (now free) staging
// smem and emit fp16 -> halves combine gather traffic (the L2 floor).
#define KCH 32
#define KP  40     // A smem row stride (fp16 elems)

template <int COLT>   // 128 or 64; fused width = 2*COLT
__global__ __launch_bounds__(256, 2)
void gemm_wmma_kernel(int useX, int wOff) {
    constexpr int WTOT = 2 * COLT;      // 256 or 128
    constexpr int CP = WTOT + 8;        // W smem stride
    constexpr int WN = WTOT / 4;        // cols per warp (64 or 32)
    constexpr int NF = WN / 16;         // 16-col frags per warp (4 or 2)
    constexpr int ABYTES = 64 * KP * 2;
    constexpr int WBYTES = KCH * CP * 2;
    constexpr int SMEM_BYTES = ABYTES + 2 * WBYTES;   // 38.9 / 22 KB
    // epilogue bounce: 4 t-warps x 32 x WN floats = 32 KB / 16 KB -> fits
    static_assert(4 * 32 * WN * 4 <= SMEM_BYTES, "bounce fits");

    __shared__ __align__(16) char smem[SMEM_BYTES];
    __half* Ah  = (__half*)smem;
    __half* Whi = (__half*)(smem + ABYTES);
    __half* Wlo = (__half*)(smem + ABYTES + WBYTES);

    const __half* ah  = useX ? g_xh : g_ah;
    const __half* wlh = g_wlh + wOff;
    const __half* wll = g_wll + wOff;
    const __half* wrh = g_wrh + wOff;
    const __half* wrl = g_wrl + wOff;

    const int tid = threadIdx.x;
    const int wid = tid >> 5;
    const int lane = tid & 31;
    const int wm = wid & 1;           // m-tile 0..1 (32 rows each)
    const int wn = wid >> 1;          // n-tile 0..3 (WN cols each)
    const int rowBase = blockIdx.x * 64;

    wmma::fragment<wmma::accumulator, 16, 16, 16, float> acc[2][NF];
#pragma unroll
    for (int m = 0; m < 2; m++)
#pragma unroll
        for (int f = 0; f < NF; f++) wmma::fill_fragment(acc[m][f], 0.0f);

    const int arow = tid >> 2;            // 0..63
    const int akq  = (tid & 3) * 8;       // k offset 0,8,16,24 (uint4 = 8 fp16)

    for (int kc = 0; kc < 128; kc += KCH) {
        {
            size_t gsrc = (size_t)(rowBase + arow) * 128 + kc + akq;
            *(uint4*)(Ah + arow * KP + akq) = *(const uint4*)(ah + gsrc);
        }
#pragma unroll
        for (int f = tid; f < KCH * (WTOT / 8); f += 256) {
            int k = f / (WTOT / 8);
            int n = (f % (WTOT / 8)) * 8;
            const __half* sh = (n < COLT) ? (wlh + (size_t)(kc + k) * COLT + n)
                                          : (wrh + (size_t)(kc + k) * COLT + (n - COLT));
            const __half* sl = (n < COLT) ? (wll + (size_t)(kc + k) * COLT + n)
                                          : (wrl + (size_t)(kc + k) * COLT + (n - COLT));
            *(uint4*)(Whi + k * CP + n) = *(const uint4*)sh;
            *(uint4*)(Wlo + k * CP + n) = *(const uint4*)sl;
        }
        __syncthreads();

#pragma unroll
        for (int kk = 0; kk < KCH; kk += 16) {
            wmma::fragment<wmma::matrix_a, 16, 16, 16, __half,
                           wmma::row_major> a0, a1;
            wmma::load_matrix_sync(a0, Ah + (wm * 32) * KP + kk, KP);
            wmma::load_matrix_sync(a1, Ah + (wm * 32 + 16) * KP + kk, KP);
#pragma unroll
            for (int f = 0; f < NF; f++) {
                wmma::fragment<wmma::matrix_b, 16, 16, 16, __half,
                               wmma::row_major> bh, bl;
                int ncol = wn * WN + f * 16;
                wmma::load_matrix_sync(bh, Whi + kk * CP + ncol, CP);
                wmma::load_matrix_sync(bl, Wlo + kk * CP + ncol, CP);
                wmma::mma_sync(acc[0][f], a0, bh, acc[0][f]);
                wmma::mma_sync(acc[1][f], a1, bh, acc[1][f]);
                wmma::mma_sync(acc[0][f], a0, bl, acc[0][f]);
                wmma::mma_sync(acc[1][f], a1, bl, acc[1][f]);
            }
        }
        __syncthreads();
    }

    if (wn < 2) {
        // ---- t half: bounce fp32 frags through smem, emit fp16 ----
        float* bw = (float*)smem + (size_t)wid * 32 * WN;   // warp-private tile
#pragma unroll
        for (int m = 0; m < 2; m++)
#pragma unroll
            for (int f = 0; f < NF; f++)
                wmma::store_matrix_sync(bw + m * 16 * WN + f * 16, acc[m][f],
                                        WN, wmma::mem_row_major);
        __syncwarp();
        constexpr int VPR = WN / 4;   // float4 vectors per row (16 or 8)
#pragma unroll
        for (int i = 0; i < VPR; i++) {
            int v = lane + 32 * i;
            int row = v / VPR;
            int col = (v % VPR) * 4;
            float4 fv = *(float4*)(bw + row * WN + col);
            __half h4[4] = {__float2half_rn(fv.x), __float2half_rn(fv.y),
                            __float2half_rn(fv.z), __float2half_rn(fv.w)};
            int rg = rowBase + wm * 32 + row;
            *(uint2*)(g_th + (size_t)rg * COLT + wn * WN + col) = *(uint2*)h4;
        }
    } else {
        // ---- r half: direct fp32 wmma store ----
#pragma unroll
        for (int m = 0; m < 2; m++) {
            int r = rowBase + wm * 32 + m * 16;
#pragma unroll
            for (int f = 0; f < NF; f++) {
                int ncol = wn * WN + f * 16 - COLT;
                wmma::store_matrix_sync(g_r + (size_t)r * COLT + ncol, acc[m][f],
                                        COLT, wmma::mem_row_major);
            }
        }
    }
}

// ---------------- aggregation + combine --------------------------------------
// Gathers fp16 t rows (half traffic), accumulates fp32.
// D==128 (hidden): writes fp16 activations to g_ah. D==64 (final): fp32 outp.
template <int D, bool RELU>
__global__ __launch_bounds__(256)
void combine_kernel(const float* __restrict__ bias, float* __restrict__ outp) {
    int gw = (blockIdx.x * blockDim.x + threadIdx.x) >> 5;
    int lane = threadIdx.x & 31;
    if (gw >= NN) return;

    int beg = g_rowoff[gw];
    int end = g_rowoff[gw + 1];
    const __half* t = g_th;

    if (D == 128) {
        float a0 = 0.f, a1 = 0.f, a2 = 0.f, a3 = 0.f;
        int j = beg;
        for (; j + 4 <= end; j += 4) {
            int s0 = g_csr[j], s1 = g_csr[j + 1], s2 = g_csr[j + 2], s3 = g_csr[j + 3];
            uint2 r0 = *(const uint2*)(t + (size_t)s0 * 128 + lane * 4);
            uint2 r1 = *(const uint2*)(t + (size_t)s1 * 128 + lane * 4);
            uint2 r2 = *(const uint2*)(t + (size_t)s2 * 128 + lane * 4);
            uint2 r3 = *(const uint2*)(t + (size_t)s3 * 128 + lane * 4);
#pragma unroll
            for (int q = 0; q < 4; q++) {
                uint2 rr = (q == 0) ? r0 : (q == 1) ? r1 : (q == 2) ? r2 : r3;
                float2 f0 = __half22float2(*(__half2*)&rr.x);
                float2 f1 = __half22float2(*(__half2*)&rr.y);
                a0 += f0.x; a1 += f0.y; a2 += f1.x; a3 += f1.y;
            }
        }
        for (; j < end; j++) {
            int s = g_csr[j];
            uint2 rr = *(const uint2*)(t + (size_t)s * 128 + lane * 4);
            float2 f0 = __half22float2(*(__half2*)&rr.x);
            float2 f1 = __half22float2(*(__half2*)&rr.y);
            a0 += f0.x; a1 += f0.y; a2 += f1.x; a3 += f1.y;
        }
        float inv = g_invdeg[gw];
        float4 rr = *(const float4*)(g_r + (size_t)gw * 128 + lane * 4);
        float o[4];
        o[0] = a0 * inv + bias[lane * 4 + 0] + rr.x;
        o[1] = a1 * inv + bias[lane * 4 + 1] + rr.y;
        o[2] = a2 * inv + bias[lane * 4 + 2] + rr.z;
        o[3] = a3 * inv + bias[lane * 4 + 3] + rr.w;
        __half h[4];
#pragma unroll
        for (int e = 0; e < 4; e++) {
            float v = RELU ? fmaxf(o[e], 0.f) : o[e];
            h[e] = __float2half_rn(v);
        }
        *(uint2*)(g_ah + (size_t)gw * 128 + lane * 4) = *(uint2*)h;
    } else {
        float a0 = 0.f, a1 = 0.f;
        int j = beg;
        for (; j + 4 <= end; j += 4) {
            int s0 = g_csr[j], s1 = g_csr[j + 1], s2 = g_csr[j + 2], s3 = g_csr[j + 3];
            unsigned r0 = *(const unsigned*)(t + (size_t)s0 * 64 + lane * 2);
            unsigned r1 = *(const unsigned*)(t + (size_t)s1 * 64 + lane * 2);
            unsigned r2 = *(const unsigned*)(t + (size_t)s2 * 64 + lane * 2);
            unsigned r3 = *(const unsigned*)(t + (size_t)s3 * 64 + lane * 2);
#pragma unroll
            for (int q = 0; q < 4; q++) {
                unsigned rr = (q == 0) ? r0 : (q == 1) ? r1 : (q == 2) ? r2 : r3;
                float2 f = __half22float2(*(__half2*)&rr);
                a0 += f.x; a1 += f.y;
            }
        }
        for (; j < end; j++) {
            int s = g_csr[j];
            unsigned rr = *(const unsigned*)(t + (size_t)s * 64 + lane * 2);
            float2 f = __half22float2(*(__half2*)&rr);
            a0 += f.x; a1 += f.y;
        }
        float inv = g_invdeg[gw];
        float2 rr = *(const float2*)(g_r + (size_t)gw * 64 + lane * 2);
        float2 o;
        o.x = a0 * inv + bias[lane * 2 + 0] + rr.x;
        o.y = a1 * inv + bias[lane * 2 + 1] + rr.y;
        if (RELU) { o.x = fmaxf(o.x, 0.f); o.y = fmaxf(o.y, 0.f); }
        *(float2*)(outp + (size_t)gw * 64 + lane * 2) = o;
    }
}

// ---------------- launch --------------------------------------------------------
extern "C" void kernel_launch(void* const* d_in, const int* in_sizes, int n_in,
                              void* d_out, int out_size) {
    const float* x    = (const float*)d_in[0];
    const void*  ei   = d_in[1];
    const float* w_l0 = (const float*)d_in[2];
    const float* b0   = (const float*)d_in[3];
    const float* w_r0 = (const float*)d_in[4];
    const float* w_l1 = (const float*)d_in[5];
    const float* b1   = (const float*)d_in[6];
    const float* w_r1 = (const float*)d_in[7];
    const float* w_l2 = (const float*)d_in[8];
    const float* b2   = (const float*)d_in[9];
    const float* w_r2 = (const float*)d_in[10];
    float* outp = (float*)d_out;

    const int gemmBlocks = (NN + 63) / 64;        // 782
    const int combBlocks = (NN * 32 + 255) / 256; // 6250

    split_x_kernel<<<(NN * 32 + 255) / 256, 256>>>(x);
    split_w_kernel<<<(WTOTAL + 255) / 256, 256>>>(w_l0, w_r0, w_l1, w_r1, w_l2, w_r2);
    count_deg_kernel<<<(EE + 255) / 256, 256>>>(ei);
    gemm_wmma_kernel<128><<<gemmBlocks, 256>>>(1, WOFF0);     // ncu slot
    blocksum_kernel<<<NBLK, 256>>>();
    scan_bsum_kernel<<<1, 256>>>();
    write_off_kernel<<<NBLK, 256>>>();
    fill_csr_kernel<<<(EE + 255) / 256, 256>>>(ei);
    combine_kernel<128, true><<<combBlocks, 256>>>(b0, nullptr);
    gemm_wmma_kernel<128><<<gemmBlocks, 256>>>(0, WOFF1);
    combine_kernel<128, true><<<combBlocks, 256>>>(b1, nullptr);
    gemm_wmma_kernel<64><<<gemmBlocks, 256>>>(0, WOFF2);
    combine_kernel<64, false><<<combBlocks, 256>>>(b2, outp);
}

// round 15
// speedup vs baseline: 1.6799x; 1.1445x over previous
#include <cuda_runtime.h>
#include <cuda_fp16.h>
#include <mma.h>
#include <stdint.h>

using namespace nvcuda;

#define NN  50000
#define EE  800000
#define NBLK 196            // ceil(NN/256)
#define NPAD (NN + 128)     // row padding: wmma stores / unguarded A reads stay in-bounds

// W storage offsets (fp16 elements): layer0 128x128, layer1 128x128, layer2 128x64
#define WOFF0 0
#define WOFF1 16384
#define WOFF2 32768
#define WTOTAL 40960

// ---------------- scratch (device globals, zero-init at load) ---------------
__device__ __align__(16) __half g_th[NPAD * 128];   // t = h @ w_l, fp16 (gather operand)
__device__ __align__(16) float  g_r[NPAD * 128];    // r = h @ w_r, fp32
__device__ __align__(16) __half g_xh[NPAD * 128];   // fp16 of x
__device__ __align__(16) __half g_ah[NPAD * 128];   // fp16 of activations
__device__ __align__(16) __half g_wl[WTOTAL];       // Wl fp16, all layers
__device__ __align__(16) __half g_wr[WTOTAL];       // Wr fp16
__device__ int   g_degc[NN];
__device__ int   g_rowoff[NN + 1];
__device__ int   g_wptr[NN];
__device__ int   g_csr[EE];
__device__ float g_invdeg[NN];
__device__ int   g_bsum[NBLK];
__device__ int   g_bpre[NBLK];

// ---------------- edge dtype probe --------------------------------------------
__device__ __forceinline__ int probe_is64(const void* ei) {
    int lane = threadIdx.x & 31;
    long long v = ((const long long*)ei)[lane];
    unsigned ok = __ballot_sync(0xffffffffu, v >= 0 && v < NN);
    return ok == 0xffffffffu;
}

__device__ __forceinline__ void load_edge(const void* ei, int e, int is64,
                                          int& s, int& d) {
    if (is64) {
        const long long* p = (const long long*)ei;
        s = (int)p[e];
        d = (int)p[EE + e];
    } else {
        const int* p = (const int*)ei;
        s = p[e];
        d = p[EE + e];
    }
    s = min(max(s, 0), NN - 1);
    d = min(max(d, 0), NN - 1);
}

// ---------------- one-time-per-launch conversions -----------------------------
__global__ void split_x_kernel(const float* __restrict__ x) {
    int i = blockIdx.x * blockDim.x + threadIdx.x;   // float4 index
    if (i >= NN * 32) return;
    float4 v = ((const float4*)x)[i];
    __half h[4];
    h[0] = __float2half_rn(v.x); h[1] = __float2half_rn(v.y);
    h[2] = __float2half_rn(v.z); h[3] = __float2half_rn(v.w);
    *(uint2*)(g_xh + (size_t)i * 4) = *(uint2*)h;
}

__global__ void split_w_kernel(const float* __restrict__ wl0, const float* __restrict__ wr0,
                               const float* __restrict__ wl1, const float* __restrict__ wr1,
                               const float* __restrict__ wl2, const float* __restrict__ wr2) {
    int idx = blockIdx.x * blockDim.x + threadIdx.x;
    if (idx >= WTOTAL) return;
    const float *wl, *wr;
    int local;
    if (idx < WOFF1)      { wl = wl0; wr = wr0; local = idx; }
    else if (idx < WOFF2) { wl = wl1; wr = wr1; local = idx - WOFF1; }
    else                  { wl = wl2; wr = wr2; local = idx - WOFF2; }
    g_wl[idx] = __float2half_rn(wl[local]);
    g_wr[idx] = __float2half_rn(wr[local]);
}

// ---------------- graph preprocessing -----------------------------------------
__global__ void count_deg_kernel(const void* __restrict__ ei) {
    int is64 = probe_is64(ei);
    int e = blockIdx.x * blockDim.x + threadIdx.x;
    if (e < EE) {
        int s, d;
        load_edge(ei, e, is64, s, d);
        atomicAdd(&g_degc[d], 1);
    }
}

__global__ void blocksum_kernel() {
    int i = blockIdx.x * 256 + threadIdx.x;
    int v = (i < NN) ? g_degc[i] : 0;
#pragma unroll
    for (int off = 16; off > 0; off >>= 1)
        v += __shfl_down_sync(0xffffffffu, v, off);
    __shared__ int ws[8];
    if ((threadIdx.x & 31) == 0) ws[threadIdx.x >> 5] = v;
    __syncthreads();
    if (threadIdx.x == 0) {
        int s = 0;
#pragma unroll
        for (int w = 0; w < 8; w++) s += ws[w];
        g_bsum[blockIdx.x] = s;
    }
}

__global__ void scan_bsum_kernel() {
    __shared__ int sh[256];
    int t = threadIdx.x;
    int v = (t < NBLK) ? g_bsum[t] : 0;
    sh[t] = v;
    __syncthreads();
#pragma unroll
    for (int off = 1; off < 256; off <<= 1) {
        int u = (t >= off) ? sh[t - off] : 0;
        __syncthreads();
        sh[t] += u;
        __syncthreads();
    }
    if (t < NBLK) g_bpre[t] = sh[t] - v;
    if (t == NBLK - 1) g_rowoff[NN] = sh[t];
}

__global__ void write_off_kernel() {
    __shared__ int sh[256];
    int t = threadIdx.x;
    int i = blockIdx.x * 256 + t;
    int v = (i < NN) ? g_degc[i] : 0;
    sh[t] = v;
    __syncthreads();
#pragma unroll
    for (int off = 1; off < 256; off <<= 1) {
        int u = (t >= off) ? sh[t - off] : 0;
        __syncthreads();
        sh[t] += u;
        __syncthreads();
    }
    if (i < NN) {
        int excl = g_bpre[blockIdx.x] + sh[t] - v;
        g_rowoff[i] = excl;
        g_wptr[i]   = excl;
        g_invdeg[i] = 1.0f / fmaxf((float)v, 1.0f);
        g_degc[i]   = 0;
    }
}

__global__ void fill_csr_kernel(const void* __restrict__ ei) {
    int is64 = probe_is64(ei);
    int e = blockIdx.x * blockDim.x + threadIdx.x;
    if (e < EE) {
        int s, d;
        load_edge(ei, e, is64, s, d);
        int p = atomicAdd(&g_wptr[d], 1);
        if (p >= 0 && p < EE) g_csr[p] = s;
    }
}

// ---------------- fused dual wmma GEMM: t(fp16) = A@Wl, r(fp32) = A@Wr -------
// Pure fp16 operands, fp32 accumulators (1 MMA term — W-lo correction dropped;
// measured error budget: A-rounding alone gave 2.7e-4, W-rounding adds a same-
// magnitude independent term -> ~4-5.5e-4, still < 1e-3).
// CTA: 64 rows x (Wl||Wr), 256 threads, 8 warps 2m x 4n; 2 CTAs/SM pinned.
#define KCH 32
#define KP  40     // A smem row stride (fp16 elems)

template <int COLT>   // 128 or 64; fused width = 2*COLT
__global__ __launch_bounds__(256, 2)
void gemm_wmma_kernel(int useX, int wOff) {
    constexpr int WTOT = 2 * COLT;      // 256 or 128
    constexpr int CP = WTOT + 8;        // W smem stride
    constexpr int WN = WTOT / 4;        // cols per warp (64 or 32)
    constexpr int NF = WN / 16;         // 16-col frags per warp (4 or 2)
    constexpr int ABYTES = 64 * KP * 2;
    constexpr int WBYTES = KCH * CP * 2;
    constexpr int BOUNCE = 4 * 32 * WN * 4;           // t-warp fp32 bounce tiles
    constexpr int SMEM_BYTES = (ABYTES + WBYTES > BOUNCE) ? (ABYTES + WBYTES) : BOUNCE;

    __shared__ __align__(16) char smem[SMEM_BYTES];
    __half* Ah = (__half*)smem;
    __half* Ws = (__half*)(smem + ABYTES);

    const __half* ah = useX ? g_xh : g_ah;
    const __half* wl = g_wl + wOff;
    const __half* wr = g_wr + wOff;

    const int tid = threadIdx.x;
    const int wid = tid >> 5;
    const int lane = tid & 31;
    const int wm = wid & 1;           // m-tile 0..1 (32 rows each)
    const int wn = wid >> 1;          // n-tile 0..3 (WN cols each)
    const int rowBase = blockIdx.x * 64;

    wmma::fragment<wmma::accumulator, 16, 16, 16, float> acc[2][NF];
#pragma unroll
    for (int m = 0; m < 2; m++)
#pragma unroll
        for (int f = 0; f < NF; f++) wmma::fill_fragment(acc[m][f], 0.0f);

    const int arow = tid >> 2;            // 0..63
    const int akq  = (tid & 3) * 8;       // k offset 0,8,16,24 (uint4 = 8 fp16)

    for (int kc = 0; kc < 128; kc += KCH) {
        {
            size_t gsrc = (size_t)(rowBase + arow) * 128 + kc + akq;
            *(uint4*)(Ah + arow * KP + akq) = *(const uint4*)(ah + gsrc);
        }
#pragma unroll
        for (int f = tid; f < KCH * (WTOT / 8); f += 256) {
            int k = f / (WTOT / 8);
            int n = (f % (WTOT / 8)) * 8;
            const __half* src = (n < COLT) ? (wl + (size_t)(kc + k) * COLT + n)
                                           : (wr + (size_t)(kc + k) * COLT + (n - COLT));
            *(uint4*)(Ws + k * CP + n) = *(const uint4*)src;
        }
        __syncthreads();

#pragma unroll
        for (int kk = 0; kk < KCH; kk += 16) {
            wmma::fragment<wmma::matrix_a, 16, 16, 16, __half,
                           wmma::row_major> a0, a1;
            wmma::load_matrix_sync(a0, Ah + (wm * 32) * KP + kk, KP);
            wmma::load_matrix_sync(a1, Ah + (wm * 32 + 16) * KP + kk, KP);
#pragma unroll
            for (int f = 0; f < NF; f++) {
                wmma::fragment<wmma::matrix_b, 16, 16, 16, __half,
                               wmma::row_major> b;
                int ncol = wn * WN + f * 16;
                wmma::load_matrix_sync(b, Ws + kk * CP + ncol, CP);
                wmma::mma_sync(acc[0][f], a0, b, acc[0][f]);
                wmma::mma_sync(acc[1][f], a1, b, acc[1][f]);
            }
        }
        __syncthreads();
    }

    if (wn < 2) {
        // ---- t half: bounce fp32 frags through smem, emit fp16 ----
        float* bw = (float*)smem + (size_t)wid * 32 * WN;   // warp-private tile
#pragma unroll
        for (int m = 0; m < 2; m++)
#pragma unroll
            for (int f = 0; f < NF; f++)
                wmma::store_matrix_sync(bw + m * 16 * WN + f * 16, acc[m][f],
                                        WN, wmma::mem_row_major);
        __syncwarp();
        constexpr int VPR = WN / 4;   // float4 vectors per row (16 or 8)
#pragma unroll
        for (int i = 0; i < VPR; i++) {
            int v = lane + 32 * i;
            int row = v / VPR;
            int col = (v % VPR) * 4;
            float4 fv = *(float4*)(bw + row * WN + col);
            __half h4[4] = {__float2half_rn(fv.x), __float2half_rn(fv.y),
                            __float2half_rn(fv.z), __float2half_rn(fv.w)};
            int rg = rowBase + wm * 32 + row;
            *(uint2*)(g_th + (size_t)rg * COLT + wn * WN + col) = *(uint2*)h4;
        }
    } else {
        // ---- r half: direct fp32 wmma store ----
#pragma unroll
        for (int m = 0; m < 2; m++) {
            int r = rowBase + wm * 32 + m * 16;
#pragma unroll
            for (int f = 0; f < NF; f++) {
                int ncol = wn * WN + f * 16 - COLT;
                wmma::store_matrix_sync(g_r + (size_t)r * COLT + ncol, acc[m][f],
                                        COLT, wmma::mem_row_major);
            }
        }
    }
}

// ---------------- aggregation + combine --------------------------------------
// Gathers fp16 t rows, accumulates fp32.
// D==128 (hidden): writes fp16 activations to g_ah. D==64 (final): fp32 outp.
template <int D, bool RELU>
__global__ __launch_bounds__(256)
void combine_kernel(const float* __restrict__ bias, float* __restrict__ outp) {
    int gw = (blockIdx.x * blockDim.x + threadIdx.x) >> 5;
    int lane = threadIdx.x & 31;
    if (gw >= NN) return;

    int beg = g_rowoff[gw];
    int end = g_rowoff[gw + 1];
    const __half* t = g_th;

    if (D == 128) {
        float a0 = 0.f, a1 = 0.f, a2 = 0.f, a3 = 0.f;
        int j = beg;
        for (; j + 4 <= end; j += 4) {
            int s0 = g_csr[j], s1 = g_csr[j + 1], s2 = g_csr[j + 2], s3 = g_csr[j + 3];
            uint2 r0 = *(const uint2*)(t + (size_t)s0 * 128 + lane * 4);
            uint2 r1 = *(const uint2*)(t + (size_t)s1 * 128 + lane * 4);
            uint2 r2 = *(const uint2*)(t + (size_t)s2 * 128 + lane * 4);
            uint2 r3 = *(const uint2*)(t + (size_t)s3 * 128 + lane * 4);
#pragma unroll
            for (int q = 0; q < 4; q++) {
                uint2 rr = (q == 0) ? r0 : (q == 1) ? r1 : (q == 2) ? r2 : r3;
                float2 f0 = __half22float2(*(__half2*)&rr.x);
                float2 f1 = __half22float2(*(__half2*)&rr.y);
                a0 += f0.x; a1 += f0.y; a2 += f1.x; a3 += f1.y;
            }
        }
        for (; j < end; j++) {
            int s = g_csr[j];
            uint2 rr = *(const uint2*)(t + (size_t)s * 128 + lane * 4);
            float2 f0 = __half22float2(*(__half2*)&rr.x);
            float2 f1 = __half22float2(*(__half2*)&rr.y);
            a0 += f0.x; a1 += f0.y; a2 += f1.x; a3 += f1.y;
        }
        float inv = g_invdeg[gw];
        float4 rr = *(const float4*)(g_r + (size_t)gw * 128 + lane * 4);
        float o[4];
        o[0] = a0 * inv + bias[lane * 4 + 0] + rr.x;
        o[1] = a1 * inv + bias[lane * 4 + 1] + rr.y;
        o[2] = a2 * inv + bias[lane * 4 + 2] + rr.z;
        o[3] = a3 * inv + bias[lane * 4 + 3] + rr.w;
        __half h[4];
#pragma unroll
        for (int e = 0; e < 4; e++) {
            float v = RELU ? fmaxf(o[e], 0.f) : o[e];
            h[e] = __float2half_rn(v);
        }
        *(uint2*)(g_ah + (size_t)gw * 128 + lane * 4) = *(uint2*)h;
    } else {
        float a0 = 0.f, a1 = 0.f;
        int j = beg;
        for (; j + 4 <= end; j += 4) {
            int s0 = g_csr[j], s1 = g_csr[j + 1], s2 = g_csr[j + 2], s3 = g_csr[j + 3];
            unsigned r0 = *(const unsigned*)(t + (size_t)s0 * 64 + lane * 2);
            unsigned r1 = *(const unsigned*)(t + (size_t)s1 * 64 + lane * 2);
            unsigned r2 = *(const unsigned*)(t + (size_t)s2 * 64 + lane * 2);
            unsigned r3 = *(const unsigned*)(t + (size_t)s3 * 64 + lane * 2);
#pragma unroll
            for (int q = 0; q < 4; q++) {
                unsigned rr = (q == 0) ? r0 : (q == 1) ? r1 : (q == 2) ? r2 : r3;
                float2 f = __half22float2(*(__half2*)&rr);
                a0 += f.x; a1 += f.y;
            }
        }
        for (; j < end; j++) {
            int s = g_csr[j];
            unsigned rr = *(const unsigned*)(t + (size_t)s * 64 + lane * 2);
            float2 f = __half22float2(*(__half2*)&rr);
            a0 += f.x; a1 += f.y;
        }
        float inv = g_invdeg[gw];
        float2 rr = *(const float2*)(g_r + (size_t)gw * 64 + lane * 2);
        float2 o;
        o.x = a0 * inv + bias[lane * 2 + 0] + rr.x;
        o.y = a1 * inv + bias[lane * 2 + 1] + rr.y;
        if (RELU) { o.x = fmaxf(o.x, 0.f); o.y = fmaxf(o.y, 0.f); }
        *(float2*)(outp + (size_t)gw * 64 + lane * 2) = o;
    }
}

// ---------------- launch --------------------------------------------------------
extern "C" void kernel_launch(void* const* d_in, const int* in_sizes, int n_in,
                              void* d_out, int out_size) {
    const float* x    = (const float*)d_in[0];
    const void*  ei   = d_in[1];
    const float* w_l0 = (const float*)d_in[2];
    const float* b0   = (const float*)d_in[3];
    const float* w_r0 = (const float*)d_in[4];
    const float* w_l1 = (const float*)d_in[5];
    const float* b1   = (const float*)d_in[6];
    const float* w_r1 = (const float*)d_in[7];
    const float* w_l2 = (const float*)d_in[8];
    const float* b2   = (const float*)d_in[9];
    const float* w_r2 = (const float*)d_in[10];
    float* outp = (float*)d_out;

    const int gemmBlocks = (NN + 63) / 64;        // 782
    const int combBlocks = (NN * 32 + 255) / 256; // 6250

    split_x_kernel<<<(NN * 32 + 255) / 256, 256>>>(x);
    split_w_kernel<<<(WTOTAL + 255) / 256, 256>>>(w_l0, w_r0, w_l1, w_r1, w_l2, w_r2);
    count_deg_kernel<<<(EE + 255) / 256, 256>>>(ei);
    gemm_wmma_kernel<128><<<gemmBlocks, 256>>>(1, WOFF0);     // ncu slot
    blocksum_kernel<<<NBLK, 256>>>();
    scan_bsum_kernel<<<1, 256>>>();
    write_off_kernel<<<NBLK, 256>>>();
    fill_csr_kernel<<<(EE + 255) / 256, 256>>>(ei);
    combine_kernel<128, true><<<combBlocks, 256>>>(b0, nullptr);
    gemm_wmma_kernel<128><<<gemmBlocks, 256>>>(0, WOFF1);
    combine_kernel<128, true><<<combBlocks, 256>>>(b1, nullptr);
    gemm_wmma_kernel<64><<<gemmBlocks, 256>>>(0, WOFF2);
    combine_kernel<64, false><<<combBlocks, 256>>>(b2, outp);
}